// round 14
// baseline (speedup 1.0000x reference)
#include <cuda_runtime.h>
#include <cuda_bf16.h>
#include <cstdint>

#define N_NODES 50000
#define N_EDGES 400000
#define D_IN    128
#define HID     256
#define BN_EPS  1e-5f
#define SCAN_T  256
#define SCAN_B  ((N_NODES + SCAN_T - 1) / SCAN_T)   // 196

// ---------------- scratch (static __device__ globals) -------------------------
__device__ int   g_is64;
__device__ int   g_deg_f[N_NODES];
__device__ int   g_deg_b[N_NODES];
__device__ int   g_off_f[N_NODES + 1];
__device__ int   g_off_b[N_NODES + 1];
__device__ int   g_cur_f[N_NODES];
__device__ int   g_cur_b[N_NODES];
__device__ int   g_adj_f[N_EDGES];
__device__ int   g_adj_b[N_EDGES];
__device__ int   g_partF[SCAN_B];
__device__ int   g_partB[SCAN_B];
__device__ int   g_poffF[SCAN_B];
__device__ int   g_poffB[SCAN_B];
__device__ __align__(16) float g_mean_f[(size_t)N_NODES * HID];
__device__ __align__(16) float g_mean_b[(size_t)N_NODES * HID];
__device__ __align__(16) float g_h2[(size_t)N_NODES * HID];   // raw (pre-BN), fp32
__device__ float g_stats[2 * HID];
__device__ __align__(16) float g_sc[HID];
__device__ __align__(16) float g_sh[HID];
// bf16 gather sources: x (converted once) and raw h1 (written by layer-1 GEMM)
__device__ __align__(16) __nv_bfloat16 g_xb[(size_t)N_NODES * D_IN];
__device__ __align__(16) __nv_bfloat16 g_h1b[(size_t)N_NODES * HID];
// prepped weights: bf16 hi/lo, layout [seg][k][256] row-major
__device__ __align__(16) __nv_bfloat16 g_Wh1[3 * 128 * 256];
__device__ __align__(16) __nv_bfloat16 g_Wl1[3 * 128 * 256];
__device__ __align__(16) __nv_bfloat16 g_Wh2[3 * 256 * 256];
__device__ __align__(16) __nv_bfloat16 g_Wl2[3 * 256 * 256];

// ---------------- helpers -------------------------------------------------------
__device__ __forceinline__ uint32_t smem_u32(const void* p) {
    uint32_t a;
    asm("{ .reg .u64 t; cvta.to.shared.u64 t, %1; cvt.u32.u64 %0, t; }" : "=r"(a) : "l"(p));
    return a;
}
__device__ __forceinline__ void cp_async16(uint32_t saddr, const void* gaddr) {
    asm volatile("{ .reg .u64 g; cvta.to.global.u64 g, %1; "
                 "cp.async.cg.shared.global [%0], [g], 16; }"
                 :: "r"(saddr), "l"(gaddr) : "memory");
}
#define CP_COMMIT() asm volatile("cp.async.commit_group;" ::: "memory")
#define CP_WAIT0()  asm volatile("cp.async.wait_group 0;" ::: "memory")
__device__ __forceinline__ void ldsm4(uint32_t addr, uint32_t& r0, uint32_t& r1,
                                      uint32_t& r2, uint32_t& r3) {
    asm volatile("ldmatrix.sync.aligned.m8n8.x4.shared.b16 {%0,%1,%2,%3}, [%4];"
                 : "=r"(r0), "=r"(r1), "=r"(r2), "=r"(r3) : "r"(addr));
}
__device__ __forceinline__ void ldsm4t(uint32_t addr, uint32_t& r0, uint32_t& r1,
                                       uint32_t& r2, uint32_t& r3) {
    asm volatile("ldmatrix.sync.aligned.m8n8.x4.trans.shared.b16 {%0,%1,%2,%3}, [%4];"
                 : "=r"(r0), "=r"(r1), "=r"(r2), "=r"(r3) : "r"(addr));
}
__device__ __forceinline__ void mma_bf16(float* c, const uint32_t* a, const uint32_t* b) {
    asm volatile(
        "mma.sync.aligned.m16n8k16.row.col.f32.bf16.bf16.f32 "
        "{%0,%1,%2,%3}, {%4,%5,%6,%7}, {%8,%9}, {%0,%1,%2,%3};"
        : "+f"(c[0]), "+f"(c[1]), "+f"(c[2]), "+f"(c[3])
        : "r"(a[0]), "r"(a[1]), "r"(a[2]), "r"(a[3]), "r"(b[0]), "r"(b[1]));
}
__device__ __forceinline__ void split2(float a, float b, uint32_t& hi, uint32_t& lo) {
    __nv_bfloat16 ha = __float2bfloat16_rn(a), hb = __float2bfloat16_rn(b);
    __nv_bfloat16 la = __float2bfloat16_rn(a - __bfloat162float(ha));
    __nv_bfloat16 lb = __float2bfloat16_rn(b - __bfloat162float(hb));
    hi = (uint32_t)__bfloat16_as_ushort(ha) | ((uint32_t)__bfloat16_as_ushort(hb) << 16);
    lo = (uint32_t)__bfloat16_as_ushort(la) | ((uint32_t)__bfloat16_as_ushort(lb) << 16);
}
__device__ __forceinline__ void bf2f8(uint4 r, float* f) {
    const __nv_bfloat162* p = reinterpret_cast<const __nv_bfloat162*>(&r);
#pragma unroll
    for (int k = 0; k < 4; k++) {
        float2 t = __bfloat1622float2(p[k]);
        f[2 * k] = t.x; f[2 * k + 1] = t.y;
    }
}
__device__ __forceinline__ void bf2f4(uint2 r, float* f) {
    const __nv_bfloat162* p = reinterpret_cast<const __nv_bfloat162*>(&r);
#pragma unroll
    for (int k = 0; k < 2; k++) {
        float2 t = __bfloat1622float2(p[k]);
        f[2 * k] = t.x; f[2 * k + 1] = t.y;
    }
}
__device__ __forceinline__ int blockInclScan(int v, int* wsum) {
    int lane = threadIdx.x & 31, w = threadIdx.x >> 5;
    int x = v;
#pragma unroll
    for (int o = 1; o < 32; o <<= 1) {
        int u = __shfl_up_sync(0xFFFFFFFFu, x, o);
        if (lane >= o) x += u;
    }
    if (lane == 31) wsum[w] = x;
    __syncthreads();
    if (threadIdx.x < 8) {
        int z = wsum[threadIdx.x];
#pragma unroll
        for (int o = 1; o < 8; o <<= 1) {
            int u = __shfl_up_sync(0xFFu, z, o);
            if ((int)threadIdx.x >= o) z += u;
        }
        wsum[threadIdx.x] = z;
    }
    __syncthreads();
    if (w > 0) x += wsum[w - 1];
    return x;
}

// ---------------- edge dtype detection (parallel) ------------------------------
__global__ void k_detect(const int* __restrict__ ei32) {
    int t = threadIdx.x;
    int nz = (ei32[2 * t + 1] != 0) ? 1 : 0;
    int any = __syncthreads_or(nz);
    if (t == 0) g_is64 = any ? 0 : 1;
}
__device__ __forceinline__ void load_edge(const int* ei32, int i, int& s, int& d) {
    if (g_is64) { s = ei32[2 * i]; d = ei32[2 * (N_EDGES + i)]; }
    else        { s = ei32[i];     d = ei32[N_EDGES + i]; }
}

// ---------------- graph build ---------------------------------------------------
__global__ void k_zero_deg() {
    int i = blockIdx.x * blockDim.x + threadIdx.x;
    if (i < N_NODES) { g_deg_f[i] = 0; g_deg_b[i] = 0; }
}
__global__ void k_count(const int* __restrict__ ei32) {
    int i = blockIdx.x * blockDim.x + threadIdx.x;
    if (i < N_EDGES) {
        int s, d; load_edge(ei32, i, s, d);
        if ((unsigned)s < N_NODES && (unsigned)d < N_NODES) {
            atomicAdd(&g_deg_b[s], 1);
            atomicAdd(&g_deg_f[d], 1);
        }
    }
}
__global__ void k_scan_partial() {
    __shared__ int sF[8], sB[8];
    int t = threadIdx.x, lane = t & 31, w = t >> 5;
    int i = blockIdx.x * SCAN_T + t;
    int vF = 0, vB = 0;
    if (i < N_NODES) { vF = g_deg_f[i]; vB = g_deg_b[i]; }
#pragma unroll
    for (int o = 16; o > 0; o >>= 1) {
        vF += __shfl_xor_sync(0xFFFFFFFFu, vF, o);
        vB += __shfl_xor_sync(0xFFFFFFFFu, vB, o);
    }
    if (lane == 0) { sF[w] = vF; sB[w] = vB; }
    __syncthreads();
    if (t == 0) {
        int a = 0, c = 0;
#pragma unroll
        for (int j = 0; j < 8; j++) { a += sF[j]; c += sB[j]; }
        g_partF[blockIdx.x] = a;
        g_partB[blockIdx.x] = c;
    }
}
__global__ void k_scan_mid() {
    __shared__ int wsum[8];
    int t = threadIdx.x;
    g_stats[t] = 0.f;                 // folded: zero layer-1 BN stats
    g_stats[t + 256] = 0.f;
    int vF = (t < SCAN_B) ? g_partF[t] : 0;
    int inclF = blockInclScan(vF, wsum);
    if (t < SCAN_B) g_poffF[t] = inclF - vF;
    if (t == 255) g_off_f[N_NODES] = inclF;
    __syncthreads();
    int vB = (t < SCAN_B) ? g_partB[t] : 0;
    int inclB = blockInclScan(vB, wsum);
    if (t < SCAN_B) g_poffB[t] = inclB - vB;
    if (t == 255) g_off_b[N_NODES] = inclB;
}
__global__ void k_scan_final() {
    __shared__ int wsum[8];
    int t = threadIdx.x;
    int i = blockIdx.x * SCAN_T + t;
    int vF = (i < N_NODES) ? g_deg_f[i] : 0;
    int inclF = blockInclScan(vF, wsum);
    if (i < N_NODES) {
        int o = inclF - vF + g_poffF[blockIdx.x];
        g_off_f[i] = o; g_cur_f[i] = o;
    }
    __syncthreads();
    int vB = (i < N_NODES) ? g_deg_b[i] : 0;
    int inclB = blockInclScan(vB, wsum);
    if (i < N_NODES) {
        int o = inclB - vB + g_poffB[blockIdx.x];
        g_off_b[i] = o; g_cur_b[i] = o;
    }
}
__global__ void k_scatter(const int* __restrict__ ei32) {
    int i = blockIdx.x * blockDim.x + threadIdx.x;
    if (i < N_EDGES) {
        int s, d; load_edge(ei32, i, s, d);
        if ((unsigned)s < N_NODES && (unsigned)d < N_NODES) {
            int p = atomicAdd(&g_cur_f[d], 1); g_adj_f[p] = s;
            int q = atomicAdd(&g_cur_b[s], 1); g_adj_b[q] = d;
        }
    }
}

// ---------------- x -> bf16 (once) -----------------------------------------------
__global__ void k_prepXb(const float* __restrict__ x) {
    int i = blockIdx.x * blockDim.x + threadIdx.x;   // N*128 threads
    g_xb[i] = __float2bfloat16_rn(x[i]);
}

// ---------------- aggregation: one warp per (node, dir), bf16 gather -------------
// D=128: gather g_xb (no affine). D=256: gather raw g_h1b, apply relu(v*sc+sh).
// Accumulate fp32, write fp32 means.
template <int D>
__global__ void k_agg(int affine) {
    constexpr int NF = D / 32;        // features per lane (4 or 8)
    int gw = (blockIdx.x * blockDim.x + threadIdx.x) >> 5;
    int lane = threadIdx.x & 31;
    if (gw >= 2 * N_NODES) return;
    int dir = (gw >= N_NODES) ? 1 : 0;
    int node = dir ? gw - N_NODES : gw;
    const __nv_bfloat16* feat = (D == 128) ? g_xb : g_h1b;
    const int* off = dir ? g_off_b : g_off_f;
    const int* adj = dir ? g_adj_b : g_adj_f;
    float* out = dir ? g_mean_b : g_mean_f;

    float sc[NF], sh[NF];
    if (affine) {
#pragma unroll
        for (int k = 0; k < NF; k += 4) {
            float4 s4 = *reinterpret_cast<const float4*>(g_sc + lane * NF + k);
            float4 h4 = *reinterpret_cast<const float4*>(g_sh + lane * NF + k);
            sc[k] = s4.x; sc[k + 1] = s4.y; sc[k + 2] = s4.z; sc[k + 3] = s4.w;
            sh[k] = h4.x; sh[k + 1] = h4.y; sh[k + 2] = h4.z; sh[k + 3] = h4.w;
        }
    }
    int s = off[node], e = off[node + 1];
    float a[NF], b[NF];
#pragma unroll
    for (int k = 0; k < NF; k++) { a[k] = 0.f; b[k] = 0.f; }

    int j = s;
    for (; j + 1 < e; j += 2) {       // 2 independent gather streams (MLP)
        int n0 = adj[j], n1 = adj[j + 1];
        float f0[NF], f1[NF];
        if (D == 128) {
            uint2 r0 = *reinterpret_cast<const uint2*>(feat + (size_t)n0 * D + lane * NF);
            uint2 r1 = *reinterpret_cast<const uint2*>(feat + (size_t)n1 * D + lane * NF);
            bf2f4(r0, f0); bf2f4(r1, f1);
        } else {
            uint4 r0 = *reinterpret_cast<const uint4*>(feat + (size_t)n0 * D + lane * NF);
            uint4 r1 = *reinterpret_cast<const uint4*>(feat + (size_t)n1 * D + lane * NF);
            bf2f8(r0, f0); bf2f8(r1, f1);
        }
        if (affine) {
#pragma unroll
            for (int k = 0; k < NF; k++) {
                f0[k] = fmaxf(f0[k] * sc[k] + sh[k], 0.f);
                f1[k] = fmaxf(f1[k] * sc[k] + sh[k], 0.f);
            }
        }
#pragma unroll
        for (int k = 0; k < NF; k++) { a[k] += f0[k]; b[k] += f1[k]; }
    }
    if (j < e) {
        int nb = adj[j];
        float f0[NF];
        if (D == 128) {
            uint2 r0 = *reinterpret_cast<const uint2*>(feat + (size_t)nb * D + lane * NF);
            bf2f4(r0, f0);
        } else {
            uint4 r0 = *reinterpret_cast<const uint4*>(feat + (size_t)nb * D + lane * NF);
            bf2f8(r0, f0);
        }
        if (affine) {
#pragma unroll
            for (int k = 0; k < NF; k++) f0[k] = fmaxf(f0[k] * sc[k] + sh[k], 0.f);
        }
#pragma unroll
        for (int k = 0; k < NF; k++) a[k] += f0[k];
    }
#pragma unroll
    for (int k = 0; k < NF; k++) a[k] += b[k];
    int cnt = e - s;
    float inv = 1.0f / (float)(cnt > 0 ? cnt : 1);
#pragma unroll
    for (int k = 0; k < NF; k++) a[k] *= inv;
#pragma unroll
    for (int k = 0; k < NF; k += 4) {
        float4 v = make_float4(a[k], a[k + 1], a[k + 2], a[k + 3]);
        *reinterpret_cast<float4*>(out + (size_t)node * D + lane * NF + k) = v;
    }
}

// ---------------- weight prep: fp32 [K,256] -> hi/lo bf16 [seg][k][256] --------
__global__ void k_prepW(const float* __restrict__ W1, const float* __restrict__ W2,
                        const float* __restrict__ W3a, const float* __restrict__ W3b,
                        int layer) {
    int K = layer ? 256 : 128;
    int seg = blockIdx.x / K;
    int k = blockIdx.x % K;
    const float* W  = seg == 0 ? W1 : seg == 1 ? W2 : W3a;
    const float* Wb = seg == 2 ? W3b : nullptr;
    __nv_bfloat16* Wh = layer ? g_Wh2 : g_Wh1;
    __nv_bfloat16* Wl = layer ? g_Wl2 : g_Wl1;
    int n = threadIdx.x;
    float v = W[(size_t)k * HID + n];
    if (Wb) v += Wb[(size_t)k * HID + n];
    __nv_bfloat16 h = __float2bfloat16_rn(v);
    __nv_bfloat16 l = __float2bfloat16_rn(v - __bfloat162float(h));
    size_t idx = (size_t)(seg * K + k) * HID + n;
    Wh[idx] = h;
    Wl[idx] = l;
}

// ---------------- pipelined mma.sync GEMM ----------------------------------------
// C[64-tile, 128-tile] = sum_seg A_seg@B_seg + bias; hi/lo split AhBh+AhBl+AlBh.
// B double-buffered via cp.async; A prefetched to regs. Layer-1 seg-3 A reads bf16
// g_h1b (affine at convert). Layer-0 output written as bf16 g_h1b; layer-1 as fp32
// g_h2. BN stats fused (from fp32 values).
#define BM 64
#define BN 128
#define BK 32
#define A_STR 40
#define B_STR 136

__global__ __launch_bounds__(256)
void k_gemm_mma(const float* __restrict__ xin,
                const float* __restrict__ ba, const float* __restrict__ bb,
                int layer) {
    __shared__ __align__(16) __nv_bfloat16 sAh[BM][A_STR];
    __shared__ __align__(16) __nv_bfloat16 sAl[BM][A_STR];
    __shared__ __align__(16) __nv_bfloat16 sBh[2][BK][B_STR];
    __shared__ __align__(16) __nv_bfloat16 sBl[2][BK][B_STR];
    __shared__ float sBias[BN];
    __shared__ float sSc[HID];
    __shared__ float sSh[HID];

    const int K = layer ? 256 : 128;
    const int KCH = K / BK;            // 4 or 8
    const int NCH = 3 * KCH;           // 12 or 24
    int tid = threadIdx.x;
    int wid = tid >> 5, lane = tid & 31;
    int m0 = blockIdx.x * BM;
    int n0b = blockIdx.y * BN;
    int wm = wid >> 2;
    int wn = wid & 3;

    if (tid < BN) sBias[tid] = ba[n0b + tid] + bb[n0b + tid];
    if (layer) { sSc[tid] = g_sc[tid]; sSh[tid] = g_sh[tid]; }

    const __nv_bfloat16* Wh = layer ? g_Wh2 : g_Wh1;
    const __nv_bfloat16* Wl = layer ? g_Wl2 : g_Wl1;
    const float* A0 = g_mean_f;
    const float* A1 = g_mean_b;

    uint32_t ahBase = smem_u32(&sAh[0][0]);
    uint32_t alBase = smem_u32(&sAl[0][0]);

    int aRow = tid >> 2, aCg = tid & 3;       // A fill: row 0..63, 8-col group
    int bK = tid >> 3, bN = (tid & 7) * 16;   // B fill: k-row 0..31, 16-col group
    int gr = m0 + aRow;
    bool rowOK = (gr < N_NODES);

    uint32_t bhS0 = smem_u32(&sBh[0][bK][bN]);
    uint32_t bhS1 = smem_u32(&sBh[1][bK][bN]);
    uint32_t blS0 = smem_u32(&sBl[0][bK][bN]);
    uint32_t blS1 = smem_u32(&sBl[1][bK][bN]);

    float acc[2][4][4];
#pragma unroll
    for (int i = 0; i < 2; i++)
#pragma unroll
        for (int j = 0; j < 4; j++)
#pragma unroll
            for (int q = 0; q < 4; q++) acc[i][j][q] = 0.f;

    // ---- prologue: B chunk 0 via cp.async, A chunk 0 (seg 0, fp32 means) to regs
    {
        size_t gidx = (size_t)bK * HID + n0b + bN;
        cp_async16(bhS0, Wh + gidx);
        cp_async16(bhS0 + 16, Wh + gidx + 8);
        cp_async16(blS0, Wl + gidx);
        cp_async16(blS0 + 16, Wl + gidx + 8);
        CP_COMMIT();
    }
    float4 v0 = make_float4(0.f, 0.f, 0.f, 0.f), v1 = v0;
    uint4 vraw = make_uint4(0, 0, 0, 0);
    if (rowOK) {
        const float* src = A0 + (size_t)gr * K + aCg * 8;
        v0 = *reinterpret_cast<const float4*>(src);
        v1 = *reinterpret_cast<const float4*>(src + 4);
    }
    CP_WAIT0();
    __syncthreads();

    for (int c = 0; c < NCH; c++) {
        int p = c & 1;
        int seg = c / KCH, kc = c - seg * KCH;
        // ---- convert A chunk c (in regs) -> smem hi/lo
        {
            float4 w0, w1;
            if (layer && seg == 2) {
                float f[8];
                bf2f8(vraw, f);
                int cb = kc * BK + aCg * 8;
#pragma unroll
                for (int k = 0; k < 8; k++)
                    f[k] = fmaxf(f[k] * sSc[cb + k] + sSh[cb + k], 0.f);
                w0 = make_float4(f[0], f[1], f[2], f[3]);
                w1 = make_float4(f[4], f[5], f[6], f[7]);
            } else {
                w0 = v0; w1 = v1;
            }
            uint4 uh, ul;
            split2(w0.x, w0.y, uh.x, ul.x);
            split2(w0.z, w0.w, uh.y, ul.y);
            split2(w1.x, w1.y, uh.z, ul.z);
            split2(w1.z, w1.w, uh.w, ul.w);
            *reinterpret_cast<uint4*>(&sAh[aRow][aCg * 8]) = uh;
            *reinterpret_cast<uint4*>(&sAl[aRow][aCg * 8]) = ul;
        }
        // ---- prefetch chunk c+1: B via cp.async (stage p^1), A to regs
        if (c + 1 < NCH) {
            size_t gidx = (size_t)((c + 1) * BK + bK) * HID + n0b + bN;
            uint32_t bh = p ? bhS0 : bhS1;
            uint32_t bl = p ? blS0 : blS1;
            cp_async16(bh, Wh + gidx);
            cp_async16(bh + 16, Wh + gidx + 8);
            cp_async16(bl, Wl + gidx);
            cp_async16(bl + 16, Wl + gidx + 8);
            CP_COMMIT();
            int seg2 = (c + 1) / KCH, kc2 = (c + 1) - seg2 * KCH;
            if (rowOK) {
                if (seg2 == 2) {
                    if (layer) {
                        vraw = *reinterpret_cast<const uint4*>(
                            g_h1b + (size_t)gr * HID + kc2 * BK + aCg * 8);
                    } else {
                        const float* src = xin + (size_t)gr * K + kc2 * BK + aCg * 8;
                        v0 = *reinterpret_cast<const float4*>(src);
                        v1 = *reinterpret_cast<const float4*>(src + 4);
                    }
                } else {
                    const float* A = seg2 ? A1 : A0;
                    const float* src = A + (size_t)gr * K + kc2 * BK + aCg * 8;
                    v0 = *reinterpret_cast<const float4*>(src);
                    v1 = *reinterpret_cast<const float4*>(src + 4);
                }
            }
        }
        __syncthreads();   // sA ready; sB stage p ready (waited previous iter)
        // ---- MMA over 2 k-steps of 16
        uint32_t bhBase = smem_u32(&sBh[p][0][0]);
        uint32_t blBase = smem_u32(&sBl[p][0][0]);
#pragma unroll
        for (int ks = 0; ks < 2; ks++) {
            uint32_t ah[2][4], al[2][4], bh[4][2], bl[4][2];
#pragma unroll
            for (int mf = 0; mf < 2; mf++) {
                uint32_t off = ((wm * 32 + mf * 16 + (lane & 15)) * A_STR
                                + ks * 16 + (lane >> 4) * 8) * 2;
                ldsm4(ahBase + off, ah[mf][0], ah[mf][1], ah[mf][2], ah[mf][3]);
                ldsm4(alBase + off, al[mf][0], al[mf][1], al[mf][2], al[mf][3]);
            }
#pragma unroll
            for (int np = 0; np < 2; np++) {
                uint32_t off = ((ks * 16 + (lane & 15)) * B_STR
                                + wn * 32 + np * 16 + (lane >> 4) * 8) * 2;
                ldsm4t(bhBase + off, bh[np * 2][0], bh[np * 2][1],
                       bh[np * 2 + 1][0], bh[np * 2 + 1][1]);
                ldsm4t(blBase + off, bl[np * 2][0], bl[np * 2][1],
                       bl[np * 2 + 1][0], bl[np * 2 + 1][1]);
            }
#pragma unroll
            for (int mf = 0; mf < 2; mf++)
#pragma unroll
                for (int nf = 0; nf < 4; nf++) {
                    mma_bf16(acc[mf][nf], ah[mf], bh[nf]);
                    mma_bf16(acc[mf][nf], ah[mf], bl[nf]);
                    mma_bf16(acc[mf][nf], al[mf], bh[nf]);
                }
        }
        CP_WAIT0();        // next B stage landed
        __syncthreads();   // safe to overwrite sA next iteration
    }

    // ---- epilogue: bias + store (bf16 h1 for layer 0, fp32 h2 for layer 1)
    //      + fused BN stats (from fp32 values)
#pragma unroll
    for (int nf = 0; nf < 4; nf++) {
        int cl = wn * 32 + nf * 8 + (lane & 3) * 2;
        float b0 = sBias[cl], b1 = sBias[cl + 1];
        float s0 = 0.f, s1 = 0.f, q0 = 0.f, q1 = 0.f;
#pragma unroll
        for (int mf = 0; mf < 2; mf++) {
            int row0 = m0 + wm * 32 + mf * 16 + (lane >> 2);
            int row1 = row0 + 8;
            float v00 = acc[mf][nf][0] + b0, v01 = acc[mf][nf][1] + b1;
            float v10 = acc[mf][nf][2] + b0, v11 = acc[mf][nf][3] + b1;
            if (row0 < N_NODES) {
                if (layer) {
                    *reinterpret_cast<float2*>(g_h2 + (size_t)row0 * HID + n0b + cl) =
                        make_float2(v00, v01);
                } else {
                    __nv_bfloat162 t;
                    t.x = __float2bfloat16_rn(v00);
                    t.y = __float2bfloat16_rn(v01);
                    *reinterpret_cast<__nv_bfloat162*>(g_h1b + (size_t)row0 * HID + n0b + cl) = t;
                }
                s0 += v00; q0 += v00 * v00; s1 += v01; q1 += v01 * v01;
            }
            if (row1 < N_NODES) {
                if (layer) {
                    *reinterpret_cast<float2*>(g_h2 + (size_t)row1 * HID + n0b + cl) =
                        make_float2(v10, v11);
                } else {
                    __nv_bfloat162 t;
                    t.x = __float2bfloat16_rn(v10);
                    t.y = __float2bfloat16_rn(v11);
                    *reinterpret_cast<__nv_bfloat162*>(g_h1b + (size_t)row1 * HID + n0b + cl) = t;
                }
                s0 += v10; q0 += v10 * v10; s1 += v11; q1 += v11 * v11;
            }
        }
#pragma unroll
        for (int o = 4; o < 32; o <<= 1) {
            s0 += __shfl_xor_sync(0xFFFFFFFFu, s0, o);
            s1 += __shfl_xor_sync(0xFFFFFFFFu, s1, o);
            q0 += __shfl_xor_sync(0xFFFFFFFFu, q0, o);
            q1 += __shfl_xor_sync(0xFFFFFFFFu, q1, o);
        }
        if (lane < 4) {
            atomicAdd(&g_stats[n0b + cl], s0);
            atomicAdd(&g_stats[n0b + cl + 1], s1);
            atomicAdd(&g_stats[HID + n0b + cl], q0);
            atomicAdd(&g_stats[HID + n0b + cl + 1], q1);
        }
    }
}

// ---------------- batchnorm finalize / max ---------------------------------------
__global__ void k_bnfinal(const float* __restrict__ g, const float* __restrict__ beta,
                          int layer, float* __restrict__ out) {
    int c = threadIdx.x;
    float mu = g_stats[c] * (1.0f / N_NODES);
    float var = g_stats[HID + c] * (1.0f / N_NODES) - mu * mu;
    float sc = g[c] * rsqrtf(var + BN_EPS);
    g_sc[c] = sc;
    g_sh[c] = beta[c] - mu * sc;
    if (layer == 0) {
        g_stats[c] = 0.f;
        g_stats[HID + c] = 0.f;
    } else {
        out[c] = 0.f;
    }
}
#define ROWS_PER_BLK 128
__global__ void k_max(float* __restrict__ out) {
    int col = threadIdx.x;
    float sc = g_sc[col], sh = g_sh[col];
    int r0 = blockIdx.x * ROWS_PER_BLK;
    int rend = r0 + ROWS_PER_BLK; if (rend > N_NODES) rend = N_NODES;
    float mx = 0.f;
    for (int r = r0; r < rend; r++) {
        float v = fmaxf(g_h2[(size_t)r * HID + col] * sc + sh, 0.f);
        if (v > mx) mx = v;
    }
    atomicMax(reinterpret_cast<int*>(out) + col, __float_as_int(mx));
}

// ---------------- launch ----------------------------------------------------------
extern "C" void kernel_launch(void* const* d_in, const int* in_sizes, int n_in,
                              void* d_out, int out_size) {
    const float* x     = (const float*)d_in[0];
    const int*   ei32  = (const int*)d_in[1];
    const float* Wl_f1 = (const float*)d_in[2];
    const float* bl_f1 = (const float*)d_in[3];
    const float* Wr_f1 = (const float*)d_in[4];
    const float* Wl_b1 = (const float*)d_in[5];
    const float* bl_b1 = (const float*)d_in[6];
    const float* Wr_b1 = (const float*)d_in[7];
    const float* Wl_f2 = (const float*)d_in[8];
    const float* bl_f2 = (const float*)d_in[9];
    const float* Wr_f2 = (const float*)d_in[10];
    const float* Wl_b2 = (const float*)d_in[11];
    const float* bl_b2 = (const float*)d_in[12];
    const float* Wr_b2 = (const float*)d_in[13];
    const float* g1    = (const float*)d_in[14];
    const float* beta1 = (const float*)d_in[15];
    const float* g2    = (const float*)d_in[16];
    const float* beta2 = (const float*)d_in[17];
    float* out = (float*)d_out;

    // ---- CSR build (scan_mid also zeroes layer-1 BN stats) ----
    k_detect<<<1, 256>>>(ei32);
    k_zero_deg<<<(N_NODES + 1023) / 1024, 1024>>>();
    k_count<<<(N_EDGES + 255) / 256, 256>>>(ei32);
    k_scan_partial<<<SCAN_B, SCAN_T>>>();
    k_scan_mid<<<1, 256>>>();
    k_scan_final<<<SCAN_B, SCAN_T>>>();
    k_scatter<<<(N_EDGES + 255) / 256, 256>>>(ei32);

    // ---- operand prep ----
    k_prepW<<<3 * 128, 256>>>(Wl_f1, Wl_b1, Wr_f1, Wr_b1, 0);
    k_prepW<<<3 * 256, 256>>>(Wl_f2, Wl_b2, Wr_f2, Wr_b2, 1);
    k_prepXb<<<(N_NODES * D_IN) / 256, 256>>>(x);

    const int aggBlocks = (2 * N_NODES + 7) / 8;        // both dirs in one launch
    dim3 gemmGrid((N_NODES + BM - 1) / BM, HID / BN);   // (782, 2)
    const int bnBlocks = (N_NODES + ROWS_PER_BLK - 1) / ROWS_PER_BLK;

    // ---- layer 1 (agg gathers bf16 x) ----
    k_agg<D_IN><<<aggBlocks, 256>>>(0);
    k_gemm_mma<<<gemmGrid, 256>>>(x, bl_f1, bl_b1, 0);   // writes bf16 h1
    k_bnfinal<<<1, HID>>>(g1, beta1, 0, out);            // re-zeroes stats

    // ---- layer 2 (agg gathers bf16 raw h1, affine on the fly) ----
    k_agg<HID><<<aggBlocks, 256>>>(1);
    k_gemm_mma<<<gemmGrid, 256>>>(x, bl_f2, bl_b2, 1);   // writes fp32 h2
    k_bnfinal<<<1, HID>>>(g2, beta2, 1, out);            // zeroes out[]
    k_max<<<bnBlocks, HID>>>(out);

    (void)in_sizes; (void)n_in; (void)out_size;
}

// round 15
// speedup vs baseline: 1.0280x; 1.0280x over previous
#include <cuda_runtime.h>
#include <cuda_bf16.h>
#include <cstdint>

#define N_NODES 50000
#define N_EDGES 400000
#define D_IN    128
#define HID     256
#define BN_EPS  1e-5f
#define SCAN_T  256
#define SCAN_B  ((N_NODES + SCAN_T - 1) / SCAN_T)   // 196

// ---------------- scratch (static __device__ globals) -------------------------
__device__ int   g_is64;
__device__ int   g_deg_f[N_NODES];
__device__ int   g_deg_b[N_NODES];
__device__ int   g_off_f[N_NODES + 1];
__device__ int   g_off_b[N_NODES + 1];
__device__ int   g_cur_f[N_NODES];
__device__ int   g_cur_b[N_NODES];
__device__ int   g_adj_f[N_EDGES];
__device__ int   g_adj_b[N_EDGES];
__device__ int   g_partF[SCAN_B];
__device__ int   g_partB[SCAN_B];
__device__ int   g_poffF[SCAN_B];
__device__ int   g_poffB[SCAN_B];
__device__ __align__(16) float g_mean_f[(size_t)N_NODES * HID];
__device__ __align__(16) float g_mean_b[(size_t)N_NODES * HID];
__device__ __align__(16) float g_h1[(size_t)N_NODES * HID];   // raw (pre-BN)
__device__ __align__(16) float g_h2[(size_t)N_NODES * HID];   // raw (pre-BN)
__device__ float g_stats[2 * HID];
__device__ __align__(16) float g_sc[HID];
__device__ __align__(16) float g_sh[HID];
// prepped weights: bf16 hi/lo, layout [seg][k][256] row-major
__device__ __align__(16) __nv_bfloat16 g_Wh1[3 * 128 * 256];
__device__ __align__(16) __nv_bfloat16 g_Wl1[3 * 128 * 256];
__device__ __align__(16) __nv_bfloat16 g_Wh2[3 * 256 * 256];
__device__ __align__(16) __nv_bfloat16 g_Wl2[3 * 256 * 256];

// ---------------- helpers -------------------------------------------------------
__device__ __forceinline__ uint32_t smem_u32(const void* p) {
    uint32_t a;
    asm("{ .reg .u64 t; cvta.to.shared.u64 t, %1; cvt.u32.u64 %0, t; }" : "=r"(a) : "l"(p));
    return a;
}
__device__ __forceinline__ void cp_async16(uint32_t saddr, const void* gaddr) {
    asm volatile("{ .reg .u64 g; cvta.to.global.u64 g, %1; "
                 "cp.async.cg.shared.global [%0], [g], 16; }"
                 :: "r"(saddr), "l"(gaddr) : "memory");
}
#define CP_COMMIT() asm volatile("cp.async.commit_group;" ::: "memory")
#define CP_WAIT0()  asm volatile("cp.async.wait_group 0;" ::: "memory")
__device__ __forceinline__ void ldsm4(uint32_t addr, uint32_t& r0, uint32_t& r1,
                                      uint32_t& r2, uint32_t& r3) {
    asm volatile("ldmatrix.sync.aligned.m8n8.x4.shared.b16 {%0,%1,%2,%3}, [%4];"
                 : "=r"(r0), "=r"(r1), "=r"(r2), "=r"(r3) : "r"(addr));
}
__device__ __forceinline__ void ldsm4t(uint32_t addr, uint32_t& r0, uint32_t& r1,
                                       uint32_t& r2, uint32_t& r3) {
    asm volatile("ldmatrix.sync.aligned.m8n8.x4.trans.shared.b16 {%0,%1,%2,%3}, [%4];"
                 : "=r"(r0), "=r"(r1), "=r"(r2), "=r"(r3) : "r"(addr));
}
__device__ __forceinline__ void mma_bf16(float* c, const uint32_t* a, const uint32_t* b) {
    asm volatile(
        "mma.sync.aligned.m16n8k16.row.col.f32.bf16.bf16.f32 "
        "{%0,%1,%2,%3}, {%4,%5,%6,%7}, {%8,%9}, {%0,%1,%2,%3};"
        : "+f"(c[0]), "+f"(c[1]), "+f"(c[2]), "+f"(c[3])
        : "r"(a[0]), "r"(a[1]), "r"(a[2]), "r"(a[3]), "r"(b[0]), "r"(b[1]));
}
__device__ __forceinline__ void split2(float a, float b, uint32_t& hi, uint32_t& lo) {
    __nv_bfloat16 ha = __float2bfloat16_rn(a), hb = __float2bfloat16_rn(b);
    __nv_bfloat16 la = __float2bfloat16_rn(a - __bfloat162float(ha));
    __nv_bfloat16 lb = __float2bfloat16_rn(b - __bfloat162float(hb));
    hi = (uint32_t)__bfloat16_as_ushort(ha) | ((uint32_t)__bfloat16_as_ushort(hb) << 16);
    lo = (uint32_t)__bfloat16_as_ushort(la) | ((uint32_t)__bfloat16_as_ushort(lb) << 16);
}
// block-wide inclusive scan of one int over 256 threads; wsum must hold 8 ints
__device__ __forceinline__ int blockInclScan(int v, int* wsum) {
    int lane = threadIdx.x & 31, w = threadIdx.x >> 5;
    int x = v;
#pragma unroll
    for (int o = 1; o < 32; o <<= 1) {
        int u = __shfl_up_sync(0xFFFFFFFFu, x, o);
        if (lane >= o) x += u;
    }
    if (lane == 31) wsum[w] = x;
    __syncthreads();
    if (threadIdx.x < 8) {
        int z = wsum[threadIdx.x];
#pragma unroll
        for (int o = 1; o < 8; o <<= 1) {
            int u = __shfl_up_sync(0xFFu, z, o);
            if ((int)threadIdx.x >= o) z += u;
        }
        wsum[threadIdx.x] = z;
    }
    __syncthreads();
    if (w > 0) x += wsum[w - 1];
    return x;
}

// ---------------- edge dtype detection (parallel) ------------------------------
__global__ void k_detect(const int* __restrict__ ei32) {
    int t = threadIdx.x;
    int nz = (ei32[2 * t + 1] != 0) ? 1 : 0;
    int any = __syncthreads_or(nz);
    if (t == 0) g_is64 = any ? 0 : 1;
}
__device__ __forceinline__ void load_edge(const int* ei32, int i, int& s, int& d) {
    if (g_is64) { s = ei32[2 * i]; d = ei32[2 * (N_EDGES + i)]; }
    else        { s = ei32[i];     d = ei32[N_EDGES + i]; }
}

// ---------------- graph build ---------------------------------------------------
__global__ void k_zero_deg() {
    int i = blockIdx.x * blockDim.x + threadIdx.x;
    if (i < N_NODES) { g_deg_f[i] = 0; g_deg_b[i] = 0; }
}
__global__ void k_count(const int* __restrict__ ei32) {
    int i = blockIdx.x * blockDim.x + threadIdx.x;
    if (i < N_EDGES) {
        int s, d; load_edge(ei32, i, s, d);
        if ((unsigned)s < N_NODES && (unsigned)d < N_NODES) {
            atomicAdd(&g_deg_b[s], 1);
            atomicAdd(&g_deg_f[d], 1);
        }
    }
}
__global__ void k_scan_partial() {
    __shared__ int sF[8], sB[8];
    int t = threadIdx.x, lane = t & 31, w = t >> 5;
    int i = blockIdx.x * SCAN_T + t;
    int vF = 0, vB = 0;
    if (i < N_NODES) { vF = g_deg_f[i]; vB = g_deg_b[i]; }
#pragma unroll
    for (int o = 16; o > 0; o >>= 1) {
        vF += __shfl_xor_sync(0xFFFFFFFFu, vF, o);
        vB += __shfl_xor_sync(0xFFFFFFFFu, vB, o);
    }
    if (lane == 0) { sF[w] = vF; sB[w] = vB; }
    __syncthreads();
    if (t == 0) {
        int a = 0, c = 0;
#pragma unroll
        for (int j = 0; j < 8; j++) { a += sF[j]; c += sB[j]; }
        g_partF[blockIdx.x] = a;
        g_partB[blockIdx.x] = c;
    }
}
__global__ void k_scan_mid() {
    __shared__ int wsum[8];
    int t = threadIdx.x;
    int vF = (t < SCAN_B) ? g_partF[t] : 0;
    int inclF = blockInclScan(vF, wsum);
    if (t < SCAN_B) g_poffF[t] = inclF - vF;
    if (t == 255) g_off_f[N_NODES] = inclF;
    __syncthreads();
    int vB = (t < SCAN_B) ? g_partB[t] : 0;
    int inclB = blockInclScan(vB, wsum);
    if (t < SCAN_B) g_poffB[t] = inclB - vB;
    if (t == 255) g_off_b[N_NODES] = inclB;
}
__global__ void k_scan_final() {
    __shared__ int wsum[8];
    int t = threadIdx.x;
    int i = blockIdx.x * SCAN_T + t;
    int vF = (i < N_NODES) ? g_deg_f[i] : 0;
    int inclF = blockInclScan(vF, wsum);
    if (i < N_NODES) {
        int o = inclF - vF + g_poffF[blockIdx.x];
        g_off_f[i] = o; g_cur_f[i] = o;
    }
    __syncthreads();
    int vB = (i < N_NODES) ? g_deg_b[i] : 0;
    int inclB = blockInclScan(vB, wsum);
    if (i < N_NODES) {
        int o = inclB - vB + g_poffB[blockIdx.x];
        g_off_b[i] = o; g_cur_b[i] = o;
    }
}
__global__ void k_scatter(const int* __restrict__ ei32) {
    int i = blockIdx.x * blockDim.x + threadIdx.x;
    if (i < N_EDGES) {
        int s, d; load_edge(ei32, i, s, d);
        if ((unsigned)s < N_NODES && (unsigned)d < N_NODES) {
            int p = atomicAdd(&g_cur_f[d], 1); g_adj_f[p] = s;
            int q = atomicAdd(&g_cur_b[s], 1); g_adj_b[q] = d;
        }
    }
}

// ---------------- aggregation: one warp per (node, dir), both dirs in one launch -
template <int D>
__global__ void k_agg(const float* __restrict__ x, int affine) {
    int gw = (blockIdx.x * blockDim.x + threadIdx.x) >> 5;
    int lane = threadIdx.x & 31;
    if (gw >= 2 * N_NODES) return;
    int dir = (gw >= N_NODES) ? 1 : 0;
    int node = dir ? gw - N_NODES : gw;
    const float* feat = affine ? g_h1 : x;
    const int* off = dir ? g_off_b : g_off_f;
    const int* adj = dir ? g_adj_b : g_adj_f;
    float* out = dir ? g_mean_b : g_mean_f;

    float4 sc0, sh0, sc1, sh1;
    if (affine) {
        sc0 = *reinterpret_cast<const float4*>(g_sc + 4 * lane);
        sh0 = *reinterpret_cast<const float4*>(g_sh + 4 * lane);
        if (D == 256) {
            sc1 = *reinterpret_cast<const float4*>(g_sc + 128 + 4 * lane);
            sh1 = *reinterpret_cast<const float4*>(g_sh + 128 + 4 * lane);
        }
    }
    int s = off[node], e = off[node + 1];
    float4 a0 = make_float4(0.f, 0.f, 0.f, 0.f);
    float4 a1 = make_float4(0.f, 0.f, 0.f, 0.f);
    float4 b0 = make_float4(0.f, 0.f, 0.f, 0.f);
    float4 b1 = make_float4(0.f, 0.f, 0.f, 0.f);
    int j = s;
    for (; j + 1 < e; j += 2) {           // 2 independent gather streams (MLP)
        int nb0 = adj[j], nb1 = adj[j + 1];
        const float4* p0 = reinterpret_cast<const float4*>(feat + (size_t)nb0 * D);
        const float4* p1 = reinterpret_cast<const float4*>(feat + (size_t)nb1 * D);
        float4 v = p0[lane];
        float4 w = p1[lane];
        if (affine) {
            v.x = fmaxf(v.x * sc0.x + sh0.x, 0.f);
            v.y = fmaxf(v.y * sc0.y + sh0.y, 0.f);
            v.z = fmaxf(v.z * sc0.z + sh0.z, 0.f);
            v.w = fmaxf(v.w * sc0.w + sh0.w, 0.f);
            w.x = fmaxf(w.x * sc0.x + sh0.x, 0.f);
            w.y = fmaxf(w.y * sc0.y + sh0.y, 0.f);
            w.z = fmaxf(w.z * sc0.z + sh0.z, 0.f);
            w.w = fmaxf(w.w * sc0.w + sh0.w, 0.f);
        }
        a0.x += v.x; a0.y += v.y; a0.z += v.z; a0.w += v.w;
        b0.x += w.x; b0.y += w.y; b0.z += w.z; b0.w += w.w;
        if (D == 256) {
            float4 u = p0[lane + 32];
            float4 t = p1[lane + 32];
            if (affine) {
                u.x = fmaxf(u.x * sc1.x + sh1.x, 0.f);
                u.y = fmaxf(u.y * sc1.y + sh1.y, 0.f);
                u.z = fmaxf(u.z * sc1.z + sh1.z, 0.f);
                u.w = fmaxf(u.w * sc1.w + sh1.w, 0.f);
                t.x = fmaxf(t.x * sc1.x + sh1.x, 0.f);
                t.y = fmaxf(t.y * sc1.y + sh1.y, 0.f);
                t.z = fmaxf(t.z * sc1.z + sh1.z, 0.f);
                t.w = fmaxf(t.w * sc1.w + sh1.w, 0.f);
            }
            a1.x += u.x; a1.y += u.y; a1.z += u.z; a1.w += u.w;
            b1.x += t.x; b1.y += t.y; b1.z += t.z; b1.w += t.w;
        }
    }
    if (j < e) {
        int nb = adj[j];
        const float4* p = reinterpret_cast<const float4*>(feat + (size_t)nb * D);
        float4 v = p[lane];
        if (affine) {
            v.x = fmaxf(v.x * sc0.x + sh0.x, 0.f);
            v.y = fmaxf(v.y * sc0.y + sh0.y, 0.f);
            v.z = fmaxf(v.z * sc0.z + sh0.z, 0.f);
            v.w = fmaxf(v.w * sc0.w + sh0.w, 0.f);
        }
        a0.x += v.x; a0.y += v.y; a0.z += v.z; a0.w += v.w;
        if (D == 256) {
            float4 u = p[lane + 32];
            if (affine) {
                u.x = fmaxf(u.x * sc1.x + sh1.x, 0.f);
                u.y = fmaxf(u.y * sc1.y + sh1.y, 0.f);
                u.z = fmaxf(u.z * sc1.z + sh1.z, 0.f);
                u.w = fmaxf(u.w * sc1.w + sh1.w, 0.f);
            }
            a1.x += u.x; a1.y += u.y; a1.z += u.z; a1.w += u.w;
        }
    }
    a0.x += b0.x; a0.y += b0.y; a0.z += b0.z; a0.w += b0.w;
    a1.x += b1.x; a1.y += b1.y; a1.z += b1.z; a1.w += b1.w;
    int cnt = e - s;
    float inv = 1.0f / (float)(cnt > 0 ? cnt : 1);
    a0.x *= inv; a0.y *= inv; a0.z *= inv; a0.w *= inv;
    float4* q = reinterpret_cast<float4*>(out + (size_t)node * D);
    q[lane] = a0;
    if (D == 256) {
        a1.x *= inv; a1.y *= inv; a1.z *= inv; a1.w *= inv;
        q[lane + 32] = a1;
    }
}

// ---------------- weight prep: fp32 [K,256] -> hi/lo bf16 [seg][k][256] --------
__global__ void k_prepW(const float* __restrict__ W1, const float* __restrict__ W2,
                        const float* __restrict__ W3a, const float* __restrict__ W3b,
                        int layer) {
    int K = layer ? 256 : 128;
    int seg = blockIdx.x / K;
    int k = blockIdx.x % K;
    const float* W  = seg == 0 ? W1 : seg == 1 ? W2 : W3a;
    const float* Wb = seg == 2 ? W3b : nullptr;
    __nv_bfloat16* Wh = layer ? g_Wh2 : g_Wh1;
    __nv_bfloat16* Wl = layer ? g_Wl2 : g_Wl1;
    int n = threadIdx.x;
    float v = W[(size_t)k * HID + n];
    if (Wb) v += Wb[(size_t)k * HID + n];
    __nv_bfloat16 h = __float2bfloat16_rn(v);
    __nv_bfloat16 l = __float2bfloat16_rn(v - __bfloat162float(h));
    size_t idx = (size_t)(seg * K + k) * HID + n;
    Wh[idx] = h;
    Wl[idx] = l;
}

// ---------------- pipelined mma.sync GEMM ----------------------------------------
// C[64-tile, 128-tile] = sum_seg A_seg@B_seg + bias; hi/lo split AhBh+AhBl+AlBh.
// B double-buffered via cp.async; A prefetched to regs. BN stats fused.
#define BM 64
#define BN 128
#define BK 32
#define A_STR 40
#define B_STR 136

__global__ __launch_bounds__(256)
void k_gemm_mma(const float* __restrict__ xin,
                const float* __restrict__ ba, const float* __restrict__ bb,
                int layer) {
    __shared__ __align__(16) __nv_bfloat16 sAh[BM][A_STR];
    __shared__ __align__(16) __nv_bfloat16 sAl[BM][A_STR];
    __shared__ __align__(16) __nv_bfloat16 sBh[2][BK][B_STR];
    __shared__ __align__(16) __nv_bfloat16 sBl[2][BK][B_STR];
    __shared__ float sBias[BN];
    __shared__ float sSc[HID];
    __shared__ float sSh[HID];

    const int K = layer ? 256 : 128;
    const int KCH = K / BK;            // 4 or 8
    const int NCH = 3 * KCH;           // 12 or 24
    int tid = threadIdx.x;
    int wid = tid >> 5, lane = tid & 31;
    int m0 = blockIdx.x * BM;
    int n0b = blockIdx.y * BN;
    int wm = wid >> 2;
    int wn = wid & 3;

    if (tid < BN) sBias[tid] = ba[n0b + tid] + bb[n0b + tid];
    if (layer) { sSc[tid] = g_sc[tid]; sSh[tid] = g_sh[tid]; }

    const __nv_bfloat16* Wh = layer ? g_Wh2 : g_Wh1;
    const __nv_bfloat16* Wl = layer ? g_Wl2 : g_Wl1;
    const float* A0 = g_mean_f;
    const float* A1 = g_mean_b;
    const float* A2 = layer ? g_h1 : xin;

    uint32_t ahBase = smem_u32(&sAh[0][0]);
    uint32_t alBase = smem_u32(&sAl[0][0]);

    int aRow = tid >> 2, aCg = tid & 3;       // A fill: row 0..63, 8-col group
    int bK = tid >> 3, bN = (tid & 7) * 16;   // B fill: k-row 0..31, 16-col group
    int gr = m0 + aRow;
    bool rowOK = (gr < N_NODES);

    uint32_t bhS0 = smem_u32(&sBh[0][bK][bN]);
    uint32_t bhS1 = smem_u32(&sBh[1][bK][bN]);
    uint32_t blS0 = smem_u32(&sBl[0][bK][bN]);
    uint32_t blS1 = smem_u32(&sBl[1][bK][bN]);

    float acc[2][4][4];
#pragma unroll
    for (int i = 0; i < 2; i++)
#pragma unroll
        for (int j = 0; j < 4; j++)
#pragma unroll
            for (int q = 0; q < 4; q++) acc[i][j][q] = 0.f;

    // ---- prologue: B chunk 0 via cp.async, A chunk 0 to regs
    {
        size_t gidx = (size_t)bK * HID + n0b + bN;
        cp_async16(bhS0, Wh + gidx);
        cp_async16(bhS0 + 16, Wh + gidx + 8);
        cp_async16(blS0, Wl + gidx);
        cp_async16(blS0 + 16, Wl + gidx + 8);
        CP_COMMIT();
    }
    float4 v0 = make_float4(0.f, 0.f, 0.f, 0.f), v1 = v0;
    if (rowOK) {
        const float* src = A0 + (size_t)gr * K + aCg * 8;
        v0 = *reinterpret_cast<const float4*>(src);
        v1 = *reinterpret_cast<const float4*>(src + 4);
    }
    CP_WAIT0();
    __syncthreads();

    for (int c = 0; c < NCH; c++) {
        int p = c & 1;
        int seg = c / KCH, kc = c - seg * KCH;
        // ---- convert A chunk c (in regs) -> smem hi/lo
        {
            float4 w0 = v0, w1 = v1;
            if (layer && seg == 2) {
                int cb = kc * BK + aCg * 8;
                w0.x = fmaxf(w0.x * sSc[cb]     + sSh[cb],     0.f);
                w0.y = fmaxf(w0.y * sSc[cb + 1] + sSh[cb + 1], 0.f);
                w0.z = fmaxf(w0.z * sSc[cb + 2] + sSh[cb + 2], 0.f);
                w0.w = fmaxf(w0.w * sSc[cb + 3] + sSh[cb + 3], 0.f);
                w1.x = fmaxf(w1.x * sSc[cb + 4] + sSh[cb + 4], 0.f);
                w1.y = fmaxf(w1.y * sSc[cb + 5] + sSh[cb + 5], 0.f);
                w1.z = fmaxf(w1.z * sSc[cb + 6] + sSh[cb + 6], 0.f);
                w1.w = fmaxf(w1.w * sSc[cb + 7] + sSh[cb + 7], 0.f);
            }
            uint4 uh, ul;
            split2(w0.x, w0.y, uh.x, ul.x);
            split2(w0.z, w0.w, uh.y, ul.y);
            split2(w1.x, w1.y, uh.z, ul.z);
            split2(w1.z, w1.w, uh.w, ul.w);
            *reinterpret_cast<uint4*>(&sAh[aRow][aCg * 8]) = uh;
            *reinterpret_cast<uint4*>(&sAl[aRow][aCg * 8]) = ul;
        }
        // ---- prefetch chunk c+1: B via cp.async (stage p^1), A to regs
        if (c + 1 < NCH) {
            size_t gidx = (size_t)((c + 1) * BK + bK) * HID + n0b + bN;
            uint32_t bh = p ? bhS0 : bhS1;
            uint32_t bl = p ? blS0 : blS1;
            cp_async16(bh, Wh + gidx);
            cp_async16(bh + 16, Wh + gidx + 8);
            cp_async16(bl, Wl + gidx);
            cp_async16(bl + 16, Wl + gidx + 8);
            CP_COMMIT();
            int seg2 = (c + 1) / KCH, kc2 = (c + 1) - seg2 * KCH;
            const float* A = (seg2 == 0) ? A0 : (seg2 == 1) ? A1 : A2;
            if (rowOK) {
                const float* src = A + (size_t)gr * K + kc2 * BK + aCg * 8;
                v0 = *reinterpret_cast<const float4*>(src);
                v1 = *reinterpret_cast<const float4*>(src + 4);
            }
        }
        __syncthreads();   // sA ready; sB stage p ready (waited previous iter)
        // ---- MMA over 2 k-steps of 16
        uint32_t bhBase = smem_u32(&sBh[p][0][0]);
        uint32_t blBase = smem_u32(&sBl[p][0][0]);
#pragma unroll
        for (int ks = 0; ks < 2; ks++) {
            uint32_t ah[2][4], al[2][4], bh[4][2], bl[4][2];
#pragma unroll
            for (int mf = 0; mf < 2; mf++) {
                uint32_t off = ((wm * 32 + mf * 16 + (lane & 15)) * A_STR
                                + ks * 16 + (lane >> 4) * 8) * 2;
                ldsm4(ahBase + off, ah[mf][0], ah[mf][1], ah[mf][2], ah[mf][3]);
                ldsm4(alBase + off, al[mf][0], al[mf][1], al[mf][2], al[mf][3]);
            }
#pragma unroll
            for (int np = 0; np < 2; np++) {
                uint32_t off = ((ks * 16 + (lane & 15)) * B_STR
                                + wn * 32 + np * 16 + (lane >> 4) * 8) * 2;
                ldsm4t(bhBase + off, bh[np * 2][0], bh[np * 2][1],
                       bh[np * 2 + 1][0], bh[np * 2 + 1][1]);
                ldsm4t(blBase + off, bl[np * 2][0], bl[np * 2][1],
                       bl[np * 2 + 1][0], bl[np * 2 + 1][1]);
            }
#pragma unroll
            for (int mf = 0; mf < 2; mf++)
#pragma unroll
                for (int nf = 0; nf < 4; nf++) {
                    mma_bf16(acc[mf][nf], ah[mf], bh[nf]);
                    mma_bf16(acc[mf][nf], ah[mf], bl[nf]);
                    mma_bf16(acc[mf][nf], al[mf], bh[nf]);
                }
        }
        CP_WAIT0();        // next B stage landed
        __syncthreads();   // safe to overwrite sA next iteration
    }

    // ---- epilogue: bias + store fp32 + fused BN stats (sum/sumsq per column)
    float* C = layer ? g_h2 : g_h1;
#pragma unroll
    for (int nf = 0; nf < 4; nf++) {
        int cl = wn * 32 + nf * 8 + (lane & 3) * 2;
        float b0 = sBias[cl], b1 = sBias[cl + 1];
        float s0 = 0.f, s1 = 0.f, q0 = 0.f, q1 = 0.f;
#pragma unroll
        for (int mf = 0; mf < 2; mf++) {
            int row0 = m0 + wm * 32 + mf * 16 + (lane >> 2);
            int row1 = row0 + 8;
            float v00 = acc[mf][nf][0] + b0, v01 = acc[mf][nf][1] + b1;
            float v10 = acc[mf][nf][2] + b0, v11 = acc[mf][nf][3] + b1;
            if (row0 < N_NODES) {
                *reinterpret_cast<float2*>(C + (size_t)row0 * HID + n0b + cl) = make_float2(v00, v01);
                s0 += v00; q0 += v00 * v00; s1 += v01; q1 += v01 * v01;
            }
            if (row1 < N_NODES) {
                *reinterpret_cast<float2*>(C + (size_t)row1 * HID + n0b + cl) = make_float2(v10, v11);
                s0 += v10; q0 += v10 * v10; s1 += v11; q1 += v11 * v11;
            }
        }
#pragma unroll
        for (int o = 4; o < 32; o <<= 1) {
            s0 += __shfl_xor_sync(0xFFFFFFFFu, s0, o);
            s1 += __shfl_xor_sync(0xFFFFFFFFu, s1, o);
            q0 += __shfl_xor_sync(0xFFFFFFFFu, q0, o);
            q1 += __shfl_xor_sync(0xFFFFFFFFu, q1, o);
        }
        if (lane < 4) {
            atomicAdd(&g_stats[n0b + cl], s0);
            atomicAdd(&g_stats[n0b + cl + 1], s1);
            atomicAdd(&g_stats[HID + n0b + cl], q0);
            atomicAdd(&g_stats[HID + n0b + cl + 1], q1);
        }
    }
}

// ---------------- batchnorm finalize / max ---------------------------------------
__global__ void k_zero_stats(float* __restrict__ out) {
    int i = threadIdx.x + blockIdx.x * blockDim.x;
    if (i < 2 * HID) g_stats[i] = 0.f;
    if (i < HID) out[i] = 0.f;
}
#define ROWS_PER_BLK 128
__global__ void k_bnfinal(const float* __restrict__ g, const float* __restrict__ beta) {
    int c = threadIdx.x;
    float mu = g_stats[c] * (1.0f / N_NODES);
    float var = g_stats[HID + c] * (1.0f / N_NODES) - mu * mu;
    float sc = g[c] * rsqrtf(var + BN_EPS);
    g_sc[c] = sc;
    g_sh[c] = beta[c] - mu * sc;
}
__global__ void k_max(float* __restrict__ out) {
    int col = threadIdx.x;
    float sc = g_sc[col], sh = g_sh[col];
    int r0 = blockIdx.x * ROWS_PER_BLK;
    int rend = r0 + ROWS_PER_BLK; if (rend > N_NODES) rend = N_NODES;
    float mx = 0.f;
    for (int r = r0; r < rend; r++) {
        float v = fmaxf(g_h2[(size_t)r * HID + col] * sc + sh, 0.f);
        if (v > mx) mx = v;
    }
    atomicMax(reinterpret_cast<int*>(out) + col, __float_as_int(mx));
}

// ---------------- launch ----------------------------------------------------------
extern "C" void kernel_launch(void* const* d_in, const int* in_sizes, int n_in,
                              void* d_out, int out_size) {
    const float* x     = (const float*)d_in[0];
    const int*   ei32  = (const int*)d_in[1];
    const float* Wl_f1 = (const float*)d_in[2];
    const float* bl_f1 = (const float*)d_in[3];
    const float* Wr_f1 = (const float*)d_in[4];
    const float* Wl_b1 = (const float*)d_in[5];
    const float* bl_b1 = (const float*)d_in[6];
    const float* Wr_b1 = (const float*)d_in[7];
    const float* Wl_f2 = (const float*)d_in[8];
    const float* bl_f2 = (const float*)d_in[9];
    const float* Wr_f2 = (const float*)d_in[10];
    const float* Wl_b2 = (const float*)d_in[11];
    const float* bl_b2 = (const float*)d_in[12];
    const float* Wr_b2 = (const float*)d_in[13];
    const float* g1    = (const float*)d_in[14];
    const float* beta1 = (const float*)d_in[15];
    const float* g2    = (const float*)d_in[16];
    const float* beta2 = (const float*)d_in[17];
    float* out = (float*)d_out;

    // ---- CSR build (parallel scan) ----
    k_detect<<<1, 256>>>(ei32);
    k_zero_deg<<<(N_NODES + 1023) / 1024, 1024>>>();
    k_count<<<(N_EDGES + 255) / 256, 256>>>(ei32);
    k_scan_partial<<<SCAN_B, SCAN_T>>>();
    k_scan_mid<<<1, 256>>>();
    k_scan_final<<<SCAN_B, SCAN_T>>>();
    k_scatter<<<(N_EDGES + 255) / 256, 256>>>(ei32);

    // ---- weight prep ----
    k_prepW<<<3 * 128, 256>>>(Wl_f1, Wl_b1, Wr_f1, Wr_b1, 0);
    k_prepW<<<3 * 256, 256>>>(Wl_f2, Wl_b2, Wr_f2, Wr_b2, 1);

    const int aggBlocks = (2 * N_NODES + 7) / 8;        // both dirs in one launch
    dim3 gemmGrid((N_NODES + BM - 1) / BM, HID / BN);   // (782, 2)
    const int bnBlocks = (N_NODES + ROWS_PER_BLK - 1) / ROWS_PER_BLK;

    // ---- layer 1 ----
    k_agg<D_IN><<<aggBlocks, 256>>>(x, 0);
    k_zero_stats<<<1, 512>>>(out);
    k_gemm_mma<<<gemmGrid, 256>>>(x, bl_f1, bl_b1, 0);
    k_bnfinal<<<1, HID>>>(g1, beta1);

    // ---- layer 2 (affine+relu applied on the fly from raw h1) ----
    k_agg<HID><<<aggBlocks, 256>>>(x, 1);
    k_zero_stats<<<1, 512>>>(out);
    k_gemm_mma<<<gemmGrid, 256>>>(x, bl_f2, bl_b2, 1);
    k_bnfinal<<<1, HID>>>(g2, beta2);
    k_max<<<bnBlocks, HID>>>(out);

    (void)in_sizes; (void)n_in; (void)out_size;
}

// round 16
// speedup vs baseline: 1.0659x; 1.0368x over previous
#include <cuda_runtime.h>
#include <cuda_bf16.h>
#include <cstdint>

#define N_NODES 50000
#define N_EDGES 400000
#define D_IN    128
#define HID     256
#define BN_EPS  1e-5f
#define SCAN_T  256
#define SCAN_B  ((N_NODES + SCAN_T - 1) / SCAN_T)   // 196

// ---------------- scratch (static __device__ globals) -------------------------
__device__ int   g_is64;
__device__ int   g_deg_f[N_NODES];
__device__ int   g_deg_b[N_NODES];
__device__ int   g_off_f[N_NODES + 1];
__device__ int   g_off_b[N_NODES + 1];
__device__ int   g_cur_f[N_NODES];
__device__ int   g_cur_b[N_NODES];
__device__ int   g_adj_f[N_EDGES];
__device__ int   g_adj_b[N_EDGES];
__device__ int   g_partF[SCAN_B];
__device__ int   g_partB[SCAN_B];
__device__ int   g_poffF[SCAN_B];
__device__ int   g_poffB[SCAN_B];
__device__ __align__(16) float g_mean_f[(size_t)N_NODES * HID];
__device__ __align__(16) float g_mean_b[(size_t)N_NODES * HID];
__device__ __align__(16) float g_h1[(size_t)N_NODES * HID];   // raw (pre-BN)
__device__ float g_stats[2 * HID];
__device__ unsigned g_cmax[HID];      // encoded per-column max of raw h2
__device__ unsigned g_cmin[HID];      // encoded per-column min of raw h2
__device__ __align__(16) float g_sc[HID];
__device__ __align__(16) float g_sh[HID];
// prepped weights: bf16 hi/lo, layout [seg][k][256] row-major
__device__ __align__(16) __nv_bfloat16 g_Wh1[3 * 128 * 256];
__device__ __align__(16) __nv_bfloat16 g_Wl1[3 * 128 * 256];
__device__ __align__(16) __nv_bfloat16 g_Wh2[3 * 256 * 256];
__device__ __align__(16) __nv_bfloat16 g_Wl2[3 * 256 * 256];

// ---------------- helpers -------------------------------------------------------
__device__ __forceinline__ uint32_t smem_u32(const void* p) {
    uint32_t a;
    asm("{ .reg .u64 t; cvta.to.shared.u64 t, %1; cvt.u32.u64 %0, t; }" : "=r"(a) : "l"(p));
    return a;
}
__device__ __forceinline__ void cp_async16(uint32_t saddr, const void* gaddr) {
    asm volatile("{ .reg .u64 g; cvta.to.global.u64 g, %1; "
                 "cp.async.cg.shared.global [%0], [g], 16; }"
                 :: "r"(saddr), "l"(gaddr) : "memory");
}
#define CP_COMMIT() asm volatile("cp.async.commit_group;" ::: "memory")
#define CP_WAIT0()  asm volatile("cp.async.wait_group 0;" ::: "memory")
__device__ __forceinline__ void ldsm4(uint32_t addr, uint32_t& r0, uint32_t& r1,
                                      uint32_t& r2, uint32_t& r3) {
    asm volatile("ldmatrix.sync.aligned.m8n8.x4.shared.b16 {%0,%1,%2,%3}, [%4];"
                 : "=r"(r0), "=r"(r1), "=r"(r2), "=r"(r3) : "r"(addr));
}
__device__ __forceinline__ void ldsm4t(uint32_t addr, uint32_t& r0, uint32_t& r1,
                                       uint32_t& r2, uint32_t& r3) {
    asm volatile("ldmatrix.sync.aligned.m8n8.x4.trans.shared.b16 {%0,%1,%2,%3}, [%4];"
                 : "=r"(r0), "=r"(r1), "=r"(r2), "=r"(r3) : "r"(addr));
}
__device__ __forceinline__ void mma_bf16(float* c, const uint32_t* a, const uint32_t* b) {
    asm volatile(
        "mma.sync.aligned.m16n8k16.row.col.f32.bf16.bf16.f32 "
        "{%0,%1,%2,%3}, {%4,%5,%6,%7}, {%8,%9}, {%0,%1,%2,%3};"
        : "+f"(c[0]), "+f"(c[1]), "+f"(c[2]), "+f"(c[3])
        : "r"(a[0]), "r"(a[1]), "r"(a[2]), "r"(a[3]), "r"(b[0]), "r"(b[1]));
}
__device__ __forceinline__ void split2(float a, float b, uint32_t& hi, uint32_t& lo) {
    __nv_bfloat16 ha = __float2bfloat16_rn(a), hb = __float2bfloat16_rn(b);
    __nv_bfloat16 la = __float2bfloat16_rn(a - __bfloat162float(ha));
    __nv_bfloat16 lb = __float2bfloat16_rn(b - __bfloat162float(hb));
    hi = (uint32_t)__bfloat16_as_ushort(ha) | ((uint32_t)__bfloat16_as_ushort(hb) << 16);
    lo = (uint32_t)__bfloat16_as_ushort(la) | ((uint32_t)__bfloat16_as_ushort(lb) << 16);
}
// order-preserving float <-> uint encoding (works for all finite/inf values)
__device__ __forceinline__ unsigned fenc(float f) {
    unsigned u = __float_as_uint(f);
    return (u & 0x80000000u) ? ~u : (u | 0x80000000u);
}
__device__ __forceinline__ float fdec(unsigned k) {
    unsigned u = (k & 0x80000000u) ? (k ^ 0x80000000u) : ~k;
    return __uint_as_float(u);
}
// block-wide inclusive scan of one int over 256 threads; wsum must hold 8 ints
__device__ __forceinline__ int blockInclScan(int v, int* wsum) {
    int lane = threadIdx.x & 31, w = threadIdx.x >> 5;
    int x = v;
#pragma unroll
    for (int o = 1; o < 32; o <<= 1) {
        int u = __shfl_up_sync(0xFFFFFFFFu, x, o);
        if (lane >= o) x += u;
    }
    if (lane == 31) wsum[w] = x;
    __syncthreads();
    if (threadIdx.x < 8) {
        int z = wsum[threadIdx.x];
#pragma unroll
        for (int o = 1; o < 8; o <<= 1) {
            int u = __shfl_up_sync(0xFFu, z, o);
            if ((int)threadIdx.x >= o) z += u;
        }
        wsum[threadIdx.x] = z;
    }
    __syncthreads();
    if (w > 0) x += wsum[w - 1];
    return x;
}

// ---------------- edge dtype detection (parallel) ------------------------------
__global__ void k_detect(const int* __restrict__ ei32) {
    int t = threadIdx.x;
    int nz = (ei32[2 * t + 1] != 0) ? 1 : 0;
    int any = __syncthreads_or(nz);
    if (t == 0) g_is64 = any ? 0 : 1;
}
__device__ __forceinline__ void load_edge(const int* ei32, int i, int& s, int& d) {
    if (g_is64) { s = ei32[2 * i]; d = ei32[2 * (N_EDGES + i)]; }
    else        { s = ei32[i];     d = ei32[N_EDGES + i]; }
}

// ---------------- graph build ---------------------------------------------------
__global__ void k_zero_deg() {
    int i = blockIdx.x * blockDim.x + threadIdx.x;
    if (i < N_NODES) { g_deg_f[i] = 0; g_deg_b[i] = 0; }
}
__global__ void k_count(const int* __restrict__ ei32) {
    int i = blockIdx.x * blockDim.x + threadIdx.x;
    if (i < N_EDGES) {
        int s, d; load_edge(ei32, i, s, d);
        if ((unsigned)s < N_NODES && (unsigned)d < N_NODES) {
            atomicAdd(&g_deg_b[s], 1);
            atomicAdd(&g_deg_f[d], 1);
        }
    }
}
__global__ void k_scan_partial() {
    __shared__ int sF[8], sB[8];
    int t = threadIdx.x, lane = t & 31, w = t >> 5;
    int i = blockIdx.x * SCAN_T + t;
    int vF = 0, vB = 0;
    if (i < N_NODES) { vF = g_deg_f[i]; vB = g_deg_b[i]; }
#pragma unroll
    for (int o = 16; o > 0; o >>= 1) {
        vF += __shfl_xor_sync(0xFFFFFFFFu, vF, o);
        vB += __shfl_xor_sync(0xFFFFFFFFu, vB, o);
    }
    if (lane == 0) { sF[w] = vF; sB[w] = vB; }
    __syncthreads();
    if (t == 0) {
        int a = 0, c = 0;
#pragma unroll
        for (int j = 0; j < 8; j++) { a += sF[j]; c += sB[j]; }
        g_partF[blockIdx.x] = a;
        g_partB[blockIdx.x] = c;
    }
}
__global__ void k_scan_mid() {
    __shared__ int wsum[8];
    int t = threadIdx.x;
    g_stats[t] = 0.f;                 // folded: zero layer-1 BN stats
    g_stats[t + 256] = 0.f;
    int vF = (t < SCAN_B) ? g_partF[t] : 0;
    int inclF = blockInclScan(vF, wsum);
    if (t < SCAN_B) g_poffF[t] = inclF - vF;
    if (t == 255) g_off_f[N_NODES] = inclF;
    __syncthreads();
    int vB = (t < SCAN_B) ? g_partB[t] : 0;
    int inclB = blockInclScan(vB, wsum);
    if (t < SCAN_B) g_poffB[t] = inclB - vB;
    if (t == 255) g_off_b[N_NODES] = inclB;
}
__global__ void k_scan_final() {
    __shared__ int wsum[8];
    int t = threadIdx.x;
    int i = blockIdx.x * SCAN_T + t;
    int vF = (i < N_NODES) ? g_deg_f[i] : 0;
    int inclF = blockInclScan(vF, wsum);
    if (i < N_NODES) {
        int o = inclF - vF + g_poffF[blockIdx.x];
        g_off_f[i] = o; g_cur_f[i] = o;
    }
    __syncthreads();
    int vB = (i < N_NODES) ? g_deg_b[i] : 0;
    int inclB = blockInclScan(vB, wsum);
    if (i < N_NODES) {
        int o = inclB - vB + g_poffB[blockIdx.x];
        g_off_b[i] = o; g_cur_b[i] = o;
    }
}
__global__ void k_scatter(const int* __restrict__ ei32) {
    int i = blockIdx.x * blockDim.x + threadIdx.x;
    if (i < N_EDGES) {
        int s, d; load_edge(ei32, i, s, d);
        if ((unsigned)s < N_NODES && (unsigned)d < N_NODES) {
            int p = atomicAdd(&g_cur_f[d], 1); g_adj_f[p] = s;
            int q = atomicAdd(&g_cur_b[s], 1); g_adj_b[q] = d;
        }
    }
}

// ---------------- aggregation: one warp per (node, dir), both dirs in one launch -
template <int D>
__global__ void k_agg(const float* __restrict__ x, int affine) {
    int gw = (blockIdx.x * blockDim.x + threadIdx.x) >> 5;
    int lane = threadIdx.x & 31;
    if (gw >= 2 * N_NODES) return;
    int dir = (gw >= N_NODES) ? 1 : 0;
    int node = dir ? gw - N_NODES : gw;
    const float* feat = affine ? g_h1 : x;
    const int* off = dir ? g_off_b : g_off_f;
    const int* adj = dir ? g_adj_b : g_adj_f;
    float* out = dir ? g_mean_b : g_mean_f;

    float4 sc0, sh0, sc1, sh1;
    if (affine) {
        sc0 = *reinterpret_cast<const float4*>(g_sc + 4 * lane);
        sh0 = *reinterpret_cast<const float4*>(g_sh + 4 * lane);
        if (D == 256) {
            sc1 = *reinterpret_cast<const float4*>(g_sc + 128 + 4 * lane);
            sh1 = *reinterpret_cast<const float4*>(g_sh + 128 + 4 * lane);
        }
    }
    int s = off[node], e = off[node + 1];
    float4 a0 = make_float4(0.f, 0.f, 0.f, 0.f);
    float4 a1 = make_float4(0.f, 0.f, 0.f, 0.f);
    float4 b0 = make_float4(0.f, 0.f, 0.f, 0.f);
    float4 b1 = make_float4(0.f, 0.f, 0.f, 0.f);
    int j = s;
    for (; j + 1 < e; j += 2) {           // 2 independent gather streams (MLP)
        int nb0 = adj[j], nb1 = adj[j + 1];
        const float4* p0 = reinterpret_cast<const float4*>(feat + (size_t)nb0 * D);
        const float4* p1 = reinterpret_cast<const float4*>(feat + (size_t)nb1 * D);
        float4 v = p0[lane];
        float4 w = p1[lane];
        if (affine) {
            v.x = fmaxf(v.x * sc0.x + sh0.x, 0.f);
            v.y = fmaxf(v.y * sc0.y + sh0.y, 0.f);
            v.z = fmaxf(v.z * sc0.z + sh0.z, 0.f);
            v.w = fmaxf(v.w * sc0.w + sh0.w, 0.f);
            w.x = fmaxf(w.x * sc0.x + sh0.x, 0.f);
            w.y = fmaxf(w.y * sc0.y + sh0.y, 0.f);
            w.z = fmaxf(w.z * sc0.z + sh0.z, 0.f);
            w.w = fmaxf(w.w * sc0.w + sh0.w, 0.f);
        }
        a0.x += v.x; a0.y += v.y; a0.z += v.z; a0.w += v.w;
        b0.x += w.x; b0.y += w.y; b0.z += w.z; b0.w += w.w;
        if (D == 256) {
            float4 u = p0[lane + 32];
            float4 t = p1[lane + 32];
            if (affine) {
                u.x = fmaxf(u.x * sc1.x + sh1.x, 0.f);
                u.y = fmaxf(u.y * sc1.y + sh1.y, 0.f);
                u.z = fmaxf(u.z * sc1.z + sh1.z, 0.f);
                u.w = fmaxf(u.w * sc1.w + sh1.w, 0.f);
                t.x = fmaxf(t.x * sc1.x + sh1.x, 0.f);
                t.y = fmaxf(t.y * sc1.y + sh1.y, 0.f);
                t.z = fmaxf(t.z * sc1.z + sh1.z, 0.f);
                t.w = fmaxf(t.w * sc1.w + sh1.w, 0.f);
            }
            a1.x += u.x; a1.y += u.y; a1.z += u.z; a1.w += u.w;
            b1.x += t.x; b1.y += t.y; b1.z += t.z; b1.w += t.w;
        }
    }
    if (j < e) {
        int nb = adj[j];
        const float4* p = reinterpret_cast<const float4*>(feat + (size_t)nb * D);
        float4 v = p[lane];
        if (affine) {
            v.x = fmaxf(v.x * sc0.x + sh0.x, 0.f);
            v.y = fmaxf(v.y * sc0.y + sh0.y, 0.f);
            v.z = fmaxf(v.z * sc0.z + sh0.z, 0.f);
            v.w = fmaxf(v.w * sc0.w + sh0.w, 0.f);
        }
        a0.x += v.x; a0.y += v.y; a0.z += v.z; a0.w += v.w;
        if (D == 256) {
            float4 u = p[lane + 32];
            if (affine) {
                u.x = fmaxf(u.x * sc1.x + sh1.x, 0.f);
                u.y = fmaxf(u.y * sc1.y + sh1.y, 0.f);
                u.z = fmaxf(u.z * sc1.z + sh1.z, 0.f);
                u.w = fmaxf(u.w * sc1.w + sh1.w, 0.f);
            }
            a1.x += u.x; a1.y += u.y; a1.z += u.z; a1.w += u.w;
        }
    }
    a0.x += b0.x; a0.y += b0.y; a0.z += b0.z; a0.w += b0.w;
    a1.x += b1.x; a1.y += b1.y; a1.z += b1.z; a1.w += b1.w;
    int cnt = e - s;
    float inv = 1.0f / (float)(cnt > 0 ? cnt : 1);
    a0.x *= inv; a0.y *= inv; a0.z *= inv; a0.w *= inv;
    float4* q = reinterpret_cast<float4*>(out + (size_t)node * D);
    q[lane] = a0;
    if (D == 256) {
        a1.x *= inv; a1.y *= inv; a1.z *= inv; a1.w *= inv;
        q[lane + 32] = a1;
    }
}

// ---------------- weight prep: fp32 [K,256] -> hi/lo bf16 [seg][k][256] --------
__global__ void k_prepW(const float* __restrict__ W1, const float* __restrict__ W2,
                        const float* __restrict__ W3a, const float* __restrict__ W3b,
                        int layer) {
    int K = layer ? 256 : 128;
    int seg = blockIdx.x / K;
    int k = blockIdx.x % K;
    const float* W  = seg == 0 ? W1 : seg == 1 ? W2 : W3a;
    const float* Wb = seg == 2 ? W3b : nullptr;
    __nv_bfloat16* Wh = layer ? g_Wh2 : g_Wh1;
    __nv_bfloat16* Wl = layer ? g_Wl2 : g_Wl1;
    int n = threadIdx.x;
    float v = W[(size_t)k * HID + n];
    if (Wb) v += Wb[(size_t)k * HID + n];
    __nv_bfloat16 h = __float2bfloat16_rn(v);
    __nv_bfloat16 l = __float2bfloat16_rn(v - __bfloat162float(h));
    size_t idx = (size_t)(seg * K + k) * HID + n;
    Wh[idx] = h;
    Wl[idx] = l;
}

// ---------------- pipelined mma.sync GEMM ----------------------------------------
// C[64-tile, 128-tile] = sum_seg A_seg@B_seg + bias; hi/lo split AhBh+AhBl+AlBh.
// B double-buffered via cp.async; A prefetched to regs. BN stats fused.
// layer 0: stores h1. layer 1: NO store — tracks per-column max/min instead.
#define BM 64
#define BN 128
#define BK 32
#define A_STR 40
#define B_STR 136

__global__ __launch_bounds__(256)
void k_gemm_mma(const float* __restrict__ xin,
                const float* __restrict__ ba, const float* __restrict__ bb,
                int layer) {
    __shared__ __align__(16) __nv_bfloat16 sAh[BM][A_STR];
    __shared__ __align__(16) __nv_bfloat16 sAl[BM][A_STR];
    __shared__ __align__(16) __nv_bfloat16 sBh[2][BK][B_STR];
    __shared__ __align__(16) __nv_bfloat16 sBl[2][BK][B_STR];
    __shared__ float sBias[BN];
    __shared__ float sSc[HID];
    __shared__ float sSh[HID];

    const int K = layer ? 256 : 128;
    const int KCH = K / BK;            // 4 or 8
    const int NCH = 3 * KCH;           // 12 or 24
    int tid = threadIdx.x;
    int wid = tid >> 5, lane = tid & 31;
    int m0 = blockIdx.x * BM;
    int n0b = blockIdx.y * BN;
    int wm = wid >> 2;
    int wn = wid & 3;

    if (tid < BN) sBias[tid] = ba[n0b + tid] + bb[n0b + tid];
    if (layer) { sSc[tid] = g_sc[tid]; sSh[tid] = g_sh[tid]; }

    const __nv_bfloat16* Wh = layer ? g_Wh2 : g_Wh1;
    const __nv_bfloat16* Wl = layer ? g_Wl2 : g_Wl1;
    const float* A0 = g_mean_f;
    const float* A1 = g_mean_b;
    const float* A2 = layer ? g_h1 : xin;

    uint32_t ahBase = smem_u32(&sAh[0][0]);
    uint32_t alBase = smem_u32(&sAl[0][0]);

    int aRow = tid >> 2, aCg = tid & 3;       // A fill: row 0..63, 8-col group
    int bK = tid >> 3, bN = (tid & 7) * 16;   // B fill: k-row 0..31, 16-col group
    int gr = m0 + aRow;
    bool rowOK = (gr < N_NODES);

    uint32_t bhS0 = smem_u32(&sBh[0][bK][bN]);
    uint32_t bhS1 = smem_u32(&sBh[1][bK][bN]);
    uint32_t blS0 = smem_u32(&sBl[0][bK][bN]);
    uint32_t blS1 = smem_u32(&sBl[1][bK][bN]);

    float acc[2][4][4];
#pragma unroll
    for (int i = 0; i < 2; i++)
#pragma unroll
        for (int j = 0; j < 4; j++)
#pragma unroll
            for (int q = 0; q < 4; q++) acc[i][j][q] = 0.f;

    // ---- prologue: B chunk 0 via cp.async, A chunk 0 to regs
    {
        size_t gidx = (size_t)bK * HID + n0b + bN;
        cp_async16(bhS0, Wh + gidx);
        cp_async16(bhS0 + 16, Wh + gidx + 8);
        cp_async16(blS0, Wl + gidx);
        cp_async16(blS0 + 16, Wl + gidx + 8);
        CP_COMMIT();
    }
    float4 v0 = make_float4(0.f, 0.f, 0.f, 0.f), v1 = v0;
    if (rowOK) {
        const float* src = A0 + (size_t)gr * K + aCg * 8;
        v0 = *reinterpret_cast<const float4*>(src);
        v1 = *reinterpret_cast<const float4*>(src + 4);
    }
    CP_WAIT0();
    __syncthreads();

    for (int c = 0; c < NCH; c++) {
        int p = c & 1;
        int seg = c / KCH, kc = c - seg * KCH;
        // ---- convert A chunk c (in regs) -> smem hi/lo
        {
            float4 w0 = v0, w1 = v1;
            if (layer && seg == 2) {
                int cb = kc * BK + aCg * 8;
                w0.x = fmaxf(w0.x * sSc[cb]     + sSh[cb],     0.f);
                w0.y = fmaxf(w0.y * sSc[cb + 1] + sSh[cb + 1], 0.f);
                w0.z = fmaxf(w0.z * sSc[cb + 2] + sSh[cb + 2], 0.f);
                w0.w = fmaxf(w0.w * sSc[cb + 3] + sSh[cb + 3], 0.f);
                w1.x = fmaxf(w1.x * sSc[cb + 4] + sSh[cb + 4], 0.f);
                w1.y = fmaxf(w1.y * sSc[cb + 5] + sSh[cb + 5], 0.f);
                w1.z = fmaxf(w1.z * sSc[cb + 6] + sSh[cb + 6], 0.f);
                w1.w = fmaxf(w1.w * sSc[cb + 7] + sSh[cb + 7], 0.f);
            }
            uint4 uh, ul;
            split2(w0.x, w0.y, uh.x, ul.x);
            split2(w0.z, w0.w, uh.y, ul.y);
            split2(w1.x, w1.y, uh.z, ul.z);
            split2(w1.z, w1.w, uh.w, ul.w);
            *reinterpret_cast<uint4*>(&sAh[aRow][aCg * 8]) = uh;
            *reinterpret_cast<uint4*>(&sAl[aRow][aCg * 8]) = ul;
        }
        // ---- prefetch chunk c+1: B via cp.async (stage p^1), A to regs
        if (c + 1 < NCH) {
            size_t gidx = (size_t)((c + 1) * BK + bK) * HID + n0b + bN;
            uint32_t bh = p ? bhS0 : bhS1;
            uint32_t bl = p ? blS0 : blS1;
            cp_async16(bh, Wh + gidx);
            cp_async16(bh + 16, Wh + gidx + 8);
            cp_async16(bl, Wl + gidx);
            cp_async16(bl + 16, Wl + gidx + 8);
            CP_COMMIT();
            int seg2 = (c + 1) / KCH, kc2 = (c + 1) - seg2 * KCH;
            const float* A = (seg2 == 0) ? A0 : (seg2 == 1) ? A1 : A2;
            if (rowOK) {
                const float* src = A + (size_t)gr * K + kc2 * BK + aCg * 8;
                v0 = *reinterpret_cast<const float4*>(src);
                v1 = *reinterpret_cast<const float4*>(src + 4);
            }
        }
        __syncthreads();   // sA ready; sB stage p ready (waited previous iter)
        // ---- MMA over 2 k-steps of 16
        uint32_t bhBase = smem_u32(&sBh[p][0][0]);
        uint32_t blBase = smem_u32(&sBl[p][0][0]);
#pragma unroll
        for (int ks = 0; ks < 2; ks++) {
            uint32_t ah[2][4], al[2][4], bh[4][2], bl[4][2];
#pragma unroll
            for (int mf = 0; mf < 2; mf++) {
                uint32_t off = ((wm * 32 + mf * 16 + (lane & 15)) * A_STR
                                + ks * 16 + (lane >> 4) * 8) * 2;
                ldsm4(ahBase + off, ah[mf][0], ah[mf][1], ah[mf][2], ah[mf][3]);
                ldsm4(alBase + off, al[mf][0], al[mf][1], al[mf][2], al[mf][3]);
            }
#pragma unroll
            for (int np = 0; np < 2; np++) {
                uint32_t off = ((ks * 16 + (lane & 15)) * B_STR
                                + wn * 32 + np * 16 + (lane >> 4) * 8) * 2;
                ldsm4t(bhBase + off, bh[np * 2][0], bh[np * 2][1],
                       bh[np * 2 + 1][0], bh[np * 2 + 1][1]);
                ldsm4t(blBase + off, bl[np * 2][0], bl[np * 2][1],
                       bl[np * 2 + 1][0], bl[np * 2 + 1][1]);
            }
#pragma unroll
            for (int mf = 0; mf < 2; mf++)
#pragma unroll
                for (int nf = 0; nf < 4; nf++) {
                    mma_bf16(acc[mf][nf], ah[mf], bh[nf]);
                    mma_bf16(acc[mf][nf], ah[mf], bl[nf]);
                    mma_bf16(acc[mf][nf], al[mf], bh[nf]);
                }
        }
        CP_WAIT0();        // next B stage landed
        __syncthreads();   // safe to overwrite sA next iteration
    }

    // ---- epilogue -------------------------------------------------------------
    // layer 0: bias + store fp32 h1 + fused BN stats.
    // layer 1: bias + fused BN stats + per-column max/min (NO store of h2).
    float* C = g_h1;
#pragma unroll
    for (int nf = 0; nf < 4; nf++) {
        int cl = wn * 32 + nf * 8 + (lane & 3) * 2;
        float b0 = sBias[cl], b1 = sBias[cl + 1];
        float s0 = 0.f, s1 = 0.f, q0 = 0.f, q1 = 0.f;
        float mx0 = -3.4e38f, mx1 = -3.4e38f, mn0 = 3.4e38f, mn1 = 3.4e38f;
#pragma unroll
        for (int mf = 0; mf < 2; mf++) {
            int row0 = m0 + wm * 32 + mf * 16 + (lane >> 2);
            int row1 = row0 + 8;
            float v00 = acc[mf][nf][0] + b0, v01 = acc[mf][nf][1] + b1;
            float v10 = acc[mf][nf][2] + b0, v11 = acc[mf][nf][3] + b1;
            if (row0 < N_NODES) {
                if (!layer)
                    *reinterpret_cast<float2*>(C + (size_t)row0 * HID + n0b + cl) = make_float2(v00, v01);
                s0 += v00; q0 += v00 * v00; s1 += v01; q1 += v01 * v01;
                mx0 = fmaxf(mx0, v00); mn0 = fminf(mn0, v00);
                mx1 = fmaxf(mx1, v01); mn1 = fminf(mn1, v01);
            }
            if (row1 < N_NODES) {
                if (!layer)
                    *reinterpret_cast<float2*>(C + (size_t)row1 * HID + n0b + cl) = make_float2(v10, v11);
                s0 += v10; q0 += v10 * v10; s1 += v11; q1 += v11 * v11;
                mx0 = fmaxf(mx0, v10); mn0 = fminf(mn0, v10);
                mx1 = fmaxf(mx1, v11); mn1 = fminf(mn1, v11);
            }
        }
#pragma unroll
        for (int o = 4; o < 32; o <<= 1) {
            s0 += __shfl_xor_sync(0xFFFFFFFFu, s0, o);
            s1 += __shfl_xor_sync(0xFFFFFFFFu, s1, o);
            q0 += __shfl_xor_sync(0xFFFFFFFFu, q0, o);
            q1 += __shfl_xor_sync(0xFFFFFFFFu, q1, o);
            if (layer) {
                mx0 = fmaxf(mx0, __shfl_xor_sync(0xFFFFFFFFu, mx0, o));
                mx1 = fmaxf(mx1, __shfl_xor_sync(0xFFFFFFFFu, mx1, o));
                mn0 = fminf(mn0, __shfl_xor_sync(0xFFFFFFFFu, mn0, o));
                mn1 = fminf(mn1, __shfl_xor_sync(0xFFFFFFFFu, mn1, o));
            }
        }
        if (lane < 4) {
            atomicAdd(&g_stats[n0b + cl], s0);
            atomicAdd(&g_stats[n0b + cl + 1], s1);
            atomicAdd(&g_stats[HID + n0b + cl], q0);
            atomicAdd(&g_stats[HID + n0b + cl + 1], q1);
            if (layer) {
                atomicMax(&g_cmax[n0b + cl], fenc(mx0));
                atomicMax(&g_cmax[n0b + cl + 1], fenc(mx1));
                atomicMin(&g_cmin[n0b + cl], fenc(mn0));
                atomicMin(&g_cmin[n0b + cl + 1], fenc(mn1));
            }
        }
    }
}

// ---------------- batchnorm finalize ----------------------------------------------
// layer 0: compute sc/sh, re-zero stats for layer 2, init column max/min.
// layer 1: compute sc/sh, write final out[c] from column max/min (monotone affine).
__global__ void k_bnfinal(const float* __restrict__ g, const float* __restrict__ beta,
                          int layer, float* __restrict__ out) {
    int c = threadIdx.x;
    float mu = g_stats[c] * (1.0f / N_NODES);
    float var = g_stats[HID + c] * (1.0f / N_NODES) - mu * mu;
    float sc = g[c] * rsqrtf(var + BN_EPS);
    float sh = beta[c] - mu * sc;
    g_sc[c] = sc;
    g_sh[c] = sh;
    if (layer == 0) {
        g_stats[c] = 0.f;
        g_stats[HID + c] = 0.f;
        g_cmax[c] = 0u;               // < encoding of any float
        g_cmin[c] = 0xFFFFFFFFu;      // > encoding of any float
    } else {
        float vmax = fdec(g_cmax[c]);
        float vmin = fdec(g_cmin[c]);
        float vext = (sc >= 0.f) ? vmax : vmin;
        out[c] = fmaxf(vext * sc + sh, 0.f);
    }
}

// ---------------- launch ----------------------------------------------------------
extern "C" void kernel_launch(void* const* d_in, const int* in_sizes, int n_in,
                              void* d_out, int out_size) {
    const float* x     = (const float*)d_in[0];
    const int*   ei32  = (const int*)d_in[1];
    const float* Wl_f1 = (const float*)d_in[2];
    const float* bl_f1 = (const float*)d_in[3];
    const float* Wr_f1 = (const float*)d_in[4];
    const float* Wl_b1 = (const float*)d_in[5];
    const float* bl_b1 = (const float*)d_in[6];
    const float* Wr_b1 = (const float*)d_in[7];
    const float* Wl_f2 = (const float*)d_in[8];
    const float* bl_f2 = (const float*)d_in[9];
    const float* Wr_f2 = (const float*)d_in[10];
    const float* Wl_b2 = (const float*)d_in[11];
    const float* bl_b2 = (const float*)d_in[12];
    const float* Wr_b2 = (const float*)d_in[13];
    const float* g1    = (const float*)d_in[14];
    const float* beta1 = (const float*)d_in[15];
    const float* g2    = (const float*)d_in[16];
    const float* beta2 = (const float*)d_in[17];
    float* out = (float*)d_out;

    // ---- CSR build (scan_mid also zeroes layer-1 BN stats) ----
    k_detect<<<1, 256>>>(ei32);
    k_zero_deg<<<(N_NODES + 1023) / 1024, 1024>>>();
    k_count<<<(N_EDGES + 255) / 256, 256>>>(ei32);
    k_scan_partial<<<SCAN_B, SCAN_T>>>();
    k_scan_mid<<<1, 256>>>();
    k_scan_final<<<SCAN_B, SCAN_T>>>();
    k_scatter<<<(N_EDGES + 255) / 256, 256>>>(ei32);

    // ---- weight prep ----
    k_prepW<<<3 * 128, 256>>>(Wl_f1, Wl_b1, Wr_f1, Wr_b1, 0);
    k_prepW<<<3 * 256, 256>>>(Wl_f2, Wl_b2, Wr_f2, Wr_b2, 1);

    const int aggBlocks = (2 * N_NODES + 7) / 8;        // both dirs in one launch
    dim3 gemmGrid((N_NODES + BM - 1) / BM, HID / BN);   // (782, 2)

    // ---- layer 1 ----
    k_agg<D_IN><<<aggBlocks, 256>>>(x, 0);
    k_gemm_mma<<<gemmGrid, 256>>>(x, bl_f1, bl_b1, 0);
    k_bnfinal<<<1, HID>>>(g1, beta1, 0, out);   // sc/sh; re-zero stats; init max/min

    // ---- layer 2 (affine+relu on the fly; h2 never materialized) ----
    k_agg<HID><<<aggBlocks, 256>>>(x, 1);
    k_gemm_mma<<<gemmGrid, 256>>>(x, bl_f2, bl_b2, 1);
    k_bnfinal<<<1, HID>>>(g2, beta2, 1, out);   // out[] written directly

    (void)in_sizes; (void)n_in; (void)out_size;
}

// round 17
// speedup vs baseline: 1.0799x; 1.0132x over previous
#include <cuda_runtime.h>
#include <cuda_bf16.h>
#include <cstdint>

#define N_NODES 50000
#define N_EDGES 400000
#define D_IN    128
#define HID     256
#define BN_EPS  1e-5f
#define SCAN_T  256
#define SCAN_B  ((N_NODES + SCAN_T - 1) / SCAN_T)   // 196

// ---------------- scratch (static __device__ globals) -------------------------
__device__ int   g_is64;
__device__ int   g_deg_f[N_NODES];
__device__ int   g_deg_b[N_NODES];
__device__ int   g_off_f[N_NODES + 1];
__device__ int   g_off_b[N_NODES + 1];
__device__ int   g_cur_f[N_NODES];
__device__ int   g_cur_b[N_NODES];
__device__ int   g_adj_f[N_EDGES];
__device__ int   g_adj_b[N_EDGES];
__device__ int   g_partF[SCAN_B];
__device__ int   g_partB[SCAN_B];
__device__ int   g_poffF[SCAN_B];
__device__ int   g_poffB[SCAN_B];
__device__ __align__(16) float g_mean_f[(size_t)N_NODES * HID];
__device__ __align__(16) float g_mean_b[(size_t)N_NODES * HID];
__device__ __align__(16) float g_h1[(size_t)N_NODES * HID];   // raw (pre-BN)
__device__ float g_stats[2 * HID];
__device__ unsigned g_cmax[HID];      // encoded per-column max of raw h2
__device__ unsigned g_cmin[HID];      // encoded per-column min of raw h2
__device__ __align__(16) float g_sc[HID];
__device__ __align__(16) float g_sh[HID];
// prepped weights: bf16 hi/lo, layout [seg][k][256] row-major
__device__ __align__(16) __nv_bfloat16 g_Wh1[3 * 128 * 256];
__device__ __align__(16) __nv_bfloat16 g_Wl1[3 * 128 * 256];
__device__ __align__(16) __nv_bfloat16 g_Wh2[3 * 256 * 256];
__device__ __align__(16) __nv_bfloat16 g_Wl2[3 * 256 * 256];

// ---------------- helpers -------------------------------------------------------
__device__ __forceinline__ uint32_t smem_u32(const void* p) {
    uint32_t a;
    asm("{ .reg .u64 t; cvta.to.shared.u64 t, %1; cvt.u32.u64 %0, t; }" : "=r"(a) : "l"(p));
    return a;
}
__device__ __forceinline__ void cp_async16(uint32_t saddr, const void* gaddr) {
    asm volatile("{ .reg .u64 g; cvta.to.global.u64 g, %1; "
                 "cp.async.cg.shared.global [%0], [g], 16; }"
                 :: "r"(saddr), "l"(gaddr) : "memory");
}
#define CP_COMMIT() asm volatile("cp.async.commit_group;" ::: "memory")
#define CP_WAIT0()  asm volatile("cp.async.wait_group 0;" ::: "memory")
__device__ __forceinline__ void ldsm4(uint32_t addr, uint32_t& r0, uint32_t& r1,
                                      uint32_t& r2, uint32_t& r3) {
    asm volatile("ldmatrix.sync.aligned.m8n8.x4.shared.b16 {%0,%1,%2,%3}, [%4];"
                 : "=r"(r0), "=r"(r1), "=r"(r2), "=r"(r3) : "r"(addr));
}
__device__ __forceinline__ void ldsm4t(uint32_t addr, uint32_t& r0, uint32_t& r1,
                                       uint32_t& r2, uint32_t& r3) {
    asm volatile("ldmatrix.sync.aligned.m8n8.x4.trans.shared.b16 {%0,%1,%2,%3}, [%4];"
                 : "=r"(r0), "=r"(r1), "=r"(r2), "=r"(r3) : "r"(addr));
}
__device__ __forceinline__ void mma_bf16(float* c, const uint32_t* a, const uint32_t* b) {
    asm volatile(
        "mma.sync.aligned.m16n8k16.row.col.f32.bf16.bf16.f32 "
        "{%0,%1,%2,%3}, {%4,%5,%6,%7}, {%8,%9}, {%0,%1,%2,%3};"
        : "+f"(c[0]), "+f"(c[1]), "+f"(c[2]), "+f"(c[3])
        : "r"(a[0]), "r"(a[1]), "r"(a[2]), "r"(a[3]), "r"(b[0]), "r"(b[1]));
}
__device__ __forceinline__ void split2(float a, float b, uint32_t& hi, uint32_t& lo) {
    __nv_bfloat16 ha = __float2bfloat16_rn(a), hb = __float2bfloat16_rn(b);
    __nv_bfloat16 la = __float2bfloat16_rn(a - __bfloat162float(ha));
    __nv_bfloat16 lb = __float2bfloat16_rn(b - __bfloat162float(hb));
    hi = (uint32_t)__bfloat16_as_ushort(ha) | ((uint32_t)__bfloat16_as_ushort(hb) << 16);
    lo = (uint32_t)__bfloat16_as_ushort(la) | ((uint32_t)__bfloat16_as_ushort(lb) << 16);
}
// order-preserving float <-> uint encoding (works for all finite/inf values)
__device__ __forceinline__ unsigned fenc(float f) {
    unsigned u = __float_as_uint(f);
    return (u & 0x80000000u) ? ~u : (u | 0x80000000u);
}
__device__ __forceinline__ float fdec(unsigned k) {
    unsigned u = (k & 0x80000000u) ? (k ^ 0x80000000u) : ~k;
    return __uint_as_float(u);
}
// block-wide inclusive scan of one int over 256 threads; wsum must hold 8 ints
__device__ __forceinline__ int blockInclScan(int v, int* wsum) {
    int lane = threadIdx.x & 31, w = threadIdx.x >> 5;
    int x = v;
#pragma unroll
    for (int o = 1; o < 32; o <<= 1) {
        int u = __shfl_up_sync(0xFFFFFFFFu, x, o);
        if (lane >= o) x += u;
    }
    if (lane == 31) wsum[w] = x;
    __syncthreads();
    if (threadIdx.x < 8) {
        int z = wsum[threadIdx.x];
#pragma unroll
        for (int o = 1; o < 8; o <<= 1) {
            int u = __shfl_up_sync(0xFFu, z, o);
            if ((int)threadIdx.x >= o) z += u;
        }
        wsum[threadIdx.x] = z;
    }
    __syncthreads();
    if (w > 0) x += wsum[w - 1];
    return x;
}

// ---------------- edge dtype detection (parallel) ------------------------------
__global__ void k_detect(const int* __restrict__ ei32) {
    int t = threadIdx.x;
    int nz = (ei32[2 * t + 1] != 0) ? 1 : 0;
    int any = __syncthreads_or(nz);
    if (t == 0) g_is64 = any ? 0 : 1;
}
__device__ __forceinline__ void load_edge(const int* ei32, int i, int& s, int& d) {
    if (g_is64) { s = ei32[2 * i]; d = ei32[2 * (N_EDGES + i)]; }
    else        { s = ei32[i];     d = ei32[N_EDGES + i]; }
}

// ---------------- graph build ---------------------------------------------------
__global__ void k_zero_deg() {
    int i = blockIdx.x * blockDim.x + threadIdx.x;
    if (i < N_NODES) { g_deg_f[i] = 0; g_deg_b[i] = 0; }
}
__global__ void k_count(const int* __restrict__ ei32) {
    int i = blockIdx.x * blockDim.x + threadIdx.x;
    if (i < N_EDGES) {
        int s, d; load_edge(ei32, i, s, d);
        if ((unsigned)s < N_NODES && (unsigned)d < N_NODES) {
            atomicAdd(&g_deg_b[s], 1);
            atomicAdd(&g_deg_f[d], 1);
        }
    }
}
__global__ void k_scan_partial() {
    __shared__ int sF[8], sB[8];
    int t = threadIdx.x, lane = t & 31, w = t >> 5;
    int i = blockIdx.x * SCAN_T + t;
    int vF = 0, vB = 0;
    if (i < N_NODES) { vF = g_deg_f[i]; vB = g_deg_b[i]; }
#pragma unroll
    for (int o = 16; o > 0; o >>= 1) {
        vF += __shfl_xor_sync(0xFFFFFFFFu, vF, o);
        vB += __shfl_xor_sync(0xFFFFFFFFu, vB, o);
    }
    if (lane == 0) { sF[w] = vF; sB[w] = vB; }
    __syncthreads();
    if (t == 0) {
        int a = 0, c = 0;
#pragma unroll
        for (int j = 0; j < 8; j++) { a += sF[j]; c += sB[j]; }
        g_partF[blockIdx.x] = a;
        g_partB[blockIdx.x] = c;
    }
}
__global__ void k_scan_mid() {
    __shared__ int wsum[8];
    int t = threadIdx.x;
    g_stats[t] = 0.f;                 // folded: zero layer-1 BN stats
    g_stats[t + 256] = 0.f;
    int vF = (t < SCAN_B) ? g_partF[t] : 0;
    int inclF = blockInclScan(vF, wsum);
    if (t < SCAN_B) g_poffF[t] = inclF - vF;
    if (t == 255) g_off_f[N_NODES] = inclF;
    __syncthreads();
    int vB = (t < SCAN_B) ? g_partB[t] : 0;
    int inclB = blockInclScan(vB, wsum);
    if (t < SCAN_B) g_poffB[t] = inclB - vB;
    if (t == 255) g_off_b[N_NODES] = inclB;
}
__global__ void k_scan_final() {
    __shared__ int wsum[8];
    int t = threadIdx.x;
    int i = blockIdx.x * SCAN_T + t;
    int vF = (i < N_NODES) ? g_deg_f[i] : 0;
    int inclF = blockInclScan(vF, wsum);
    if (i < N_NODES) {
        int o = inclF - vF + g_poffF[blockIdx.x];
        g_off_f[i] = o; g_cur_f[i] = o;
    }
    __syncthreads();
    int vB = (i < N_NODES) ? g_deg_b[i] : 0;
    int inclB = blockInclScan(vB, wsum);
    if (i < N_NODES) {
        int o = inclB - vB + g_poffB[blockIdx.x];
        g_off_b[i] = o; g_cur_b[i] = o;
    }
}
__global__ void k_scatter(const int* __restrict__ ei32) {
    int i = blockIdx.x * blockDim.x + threadIdx.x;
    if (i < N_EDGES) {
        int s, d; load_edge(ei32, i, s, d);
        if ((unsigned)s < N_NODES && (unsigned)d < N_NODES) {
            int p = atomicAdd(&g_cur_f[d], 1); g_adj_f[p] = s;
            int q = atomicAdd(&g_cur_b[s], 1); g_adj_b[q] = d;
        }
    }
}

// ---------------- aggregation: one warp per (node, dir), both dirs in one launch -
// D=128: gather unrolled x4 (4 independent streams). D=256: unrolled x2 (reg budget).
template <int D>
__global__ void k_agg(const float* __restrict__ x, int affine) {
    int gw = (blockIdx.x * blockDim.x + threadIdx.x) >> 5;
    int lane = threadIdx.x & 31;
    if (gw >= 2 * N_NODES) return;
    int dir = (gw >= N_NODES) ? 1 : 0;
    int node = dir ? gw - N_NODES : gw;
    const float* feat = affine ? g_h1 : x;
    const int* off = dir ? g_off_b : g_off_f;
    const int* adj = dir ? g_adj_b : g_adj_f;
    float* out = dir ? g_mean_b : g_mean_f;

    float4 sc0, sh0, sc1, sh1;
    if (affine) {
        sc0 = *reinterpret_cast<const float4*>(g_sc + 4 * lane);
        sh0 = *reinterpret_cast<const float4*>(g_sh + 4 * lane);
        if (D == 256) {
            sc1 = *reinterpret_cast<const float4*>(g_sc + 128 + 4 * lane);
            sh1 = *reinterpret_cast<const float4*>(g_sh + 128 + 4 * lane);
        }
    }
    int s = off[node], e = off[node + 1];

    if (D == 128) {
        // ---- unroll x4, 4 independent accumulators (layer-1: no affine in practice)
        float4 a = make_float4(0.f, 0.f, 0.f, 0.f);
        float4 b = a, c = a, d4 = a;
        int j = s;
        for (; j + 3 < e; j += 4) {
            int n0 = adj[j], n1 = adj[j + 1], n2 = adj[j + 2], n3 = adj[j + 3];
            float4 v0 = reinterpret_cast<const float4*>(feat + (size_t)n0 * D)[lane];
            float4 v1 = reinterpret_cast<const float4*>(feat + (size_t)n1 * D)[lane];
            float4 v2 = reinterpret_cast<const float4*>(feat + (size_t)n2 * D)[lane];
            float4 v3 = reinterpret_cast<const float4*>(feat + (size_t)n3 * D)[lane];
            a.x += v0.x; a.y += v0.y; a.z += v0.z; a.w += v0.w;
            b.x += v1.x; b.y += v1.y; b.z += v1.z; b.w += v1.w;
            c.x += v2.x; c.y += v2.y; c.z += v2.z; c.w += v2.w;
            d4.x += v3.x; d4.y += v3.y; d4.z += v3.z; d4.w += v3.w;
        }
        for (; j < e; j++) {
            int nb = adj[j];
            float4 v = reinterpret_cast<const float4*>(feat + (size_t)nb * D)[lane];
            a.x += v.x; a.y += v.y; a.z += v.z; a.w += v.w;
        }
        a.x += b.x + c.x + d4.x;
        a.y += b.y + c.y + d4.y;
        a.z += b.z + c.z + d4.z;
        a.w += b.w + c.w + d4.w;
        int cnt = e - s;
        float inv = 1.0f / (float)(cnt > 0 ? cnt : 1);
        a.x *= inv; a.y *= inv; a.z *= inv; a.w *= inv;
        reinterpret_cast<float4*>(out + (size_t)node * D)[lane] = a;
        return;
    }

    // ---- D == 256: proven unroll x2 path
    float4 a0 = make_float4(0.f, 0.f, 0.f, 0.f);
    float4 a1 = make_float4(0.f, 0.f, 0.f, 0.f);
    float4 b0 = make_float4(0.f, 0.f, 0.f, 0.f);
    float4 b1 = make_float4(0.f, 0.f, 0.f, 0.f);
    int j = s;
    for (; j + 1 < e; j += 2) {           // 2 independent gather streams (MLP)
        int nb0 = adj[j], nb1 = adj[j + 1];
        const float4* p0 = reinterpret_cast<const float4*>(feat + (size_t)nb0 * D);
        const float4* p1 = reinterpret_cast<const float4*>(feat + (size_t)nb1 * D);
        float4 v = p0[lane];
        float4 w = p1[lane];
        if (affine) {
            v.x = fmaxf(v.x * sc0.x + sh0.x, 0.f);
            v.y = fmaxf(v.y * sc0.y + sh0.y, 0.f);
            v.z = fmaxf(v.z * sc0.z + sh0.z, 0.f);
            v.w = fmaxf(v.w * sc0.w + sh0.w, 0.f);
            w.x = fmaxf(w.x * sc0.x + sh0.x, 0.f);
            w.y = fmaxf(w.y * sc0.y + sh0.y, 0.f);
            w.z = fmaxf(w.z * sc0.z + sh0.z, 0.f);
            w.w = fmaxf(w.w * sc0.w + sh0.w, 0.f);
        }
        a0.x += v.x; a0.y += v.y; a0.z += v.z; a0.w += v.w;
        b0.x += w.x; b0.y += w.y; b0.z += w.z; b0.w += w.w;
        float4 u = p0[lane + 32];
        float4 t = p1[lane + 32];
        if (affine) {
            u.x = fmaxf(u.x * sc1.x + sh1.x, 0.f);
            u.y = fmaxf(u.y * sc1.y + sh1.y, 0.f);
            u.z = fmaxf(u.z * sc1.z + sh1.z, 0.f);
            u.w = fmaxf(u.w * sc1.w + sh1.w, 0.f);
            t.x = fmaxf(t.x * sc1.x + sh1.x, 0.f);
            t.y = fmaxf(t.y * sc1.y + sh1.y, 0.f);
            t.z = fmaxf(t.z * sc1.z + sh1.z, 0.f);
            t.w = fmaxf(t.w * sc1.w + sh1.w, 0.f);
        }
        a1.x += u.x; a1.y += u.y; a1.z += u.z; a1.w += u.w;
        b1.x += t.x; b1.y += t.y; b1.z += t.z; b1.w += t.w;
    }
    if (j < e) {
        int nb = adj[j];
        const float4* p = reinterpret_cast<const float4*>(feat + (size_t)nb * D);
        float4 v = p[lane];
        if (affine) {
            v.x = fmaxf(v.x * sc0.x + sh0.x, 0.f);
            v.y = fmaxf(v.y * sc0.y + sh0.y, 0.f);
            v.z = fmaxf(v.z * sc0.z + sh0.z, 0.f);
            v.w = fmaxf(v.w * sc0.w + sh0.w, 0.f);
        }
        a0.x += v.x; a0.y += v.y; a0.z += v.z; a0.w += v.w;
        float4 u = p[lane + 32];
        if (affine) {
            u.x = fmaxf(u.x * sc1.x + sh1.x, 0.f);
            u.y = fmaxf(u.y * sc1.y + sh1.y, 0.f);
            u.z = fmaxf(u.z * sc1.z + sh1.z, 0.f);
            u.w = fmaxf(u.w * sc1.w + sh1.w, 0.f);
        }
        a1.x += u.x; a1.y += u.y; a1.z += u.z; a1.w += u.w;
    }
    a0.x += b0.x; a0.y += b0.y; a0.z += b0.z; a0.w += b0.w;
    a1.x += b1.x; a1.y += b1.y; a1.z += b1.z; a1.w += b1.w;
    int cnt = e - s;
    float inv = 1.0f / (float)(cnt > 0 ? cnt : 1);
    a0.x *= inv; a0.y *= inv; a0.z *= inv; a0.w *= inv;
    float4* q = reinterpret_cast<float4*>(out + (size_t)node * D);
    q[lane] = a0;
    a1.x *= inv; a1.y *= inv; a1.z *= inv; a1.w *= inv;
    q[lane + 32] = a1;
}

// ---------------- weight prep: fp32 [K,256] -> hi/lo bf16 [seg][k][256] --------
__global__ void k_prepW(const float* __restrict__ W1, const float* __restrict__ W2,
                        const float* __restrict__ W3a, const float* __restrict__ W3b,
                        int layer) {
    int K = layer ? 256 : 128;
    int seg = blockIdx.x / K;
    int k = blockIdx.x % K;
    const float* W  = seg == 0 ? W1 : seg == 1 ? W2 : W3a;
    const float* Wb = seg == 2 ? W3b : nullptr;
    __nv_bfloat16* Wh = layer ? g_Wh2 : g_Wh1;
    __nv_bfloat16* Wl = layer ? g_Wl2 : g_Wl1;
    int n = threadIdx.x;
    float v = W[(size_t)k * HID + n];
    if (Wb) v += Wb[(size_t)k * HID + n];
    __nv_bfloat16 h = __float2bfloat16_rn(v);
    __nv_bfloat16 l = __float2bfloat16_rn(v - __bfloat162float(h));
    size_t idx = (size_t)(seg * K + k) * HID + n;
    Wh[idx] = h;
    Wl[idx] = l;
}

// ---------------- pipelined mma.sync GEMM ----------------------------------------
// C[64-tile, 128-tile] = sum_seg A_seg@B_seg + bias; hi/lo split AhBh+AhBl+AlBh.
// B double-buffered via cp.async; A prefetched to regs. BN stats fused.
// layer 0: stores h1. layer 1: NO store — tracks per-column max/min instead.
#define BM 64
#define BN 128
#define BK 32
#define A_STR 40
#define B_STR 136

__global__ __launch_bounds__(256)
void k_gemm_mma(const float* __restrict__ xin,
                const float* __restrict__ ba, const float* __restrict__ bb,
                int layer) {
    __shared__ __align__(16) __nv_bfloat16 sAh[BM][A_STR];
    __shared__ __align__(16) __nv_bfloat16 sAl[BM][A_STR];
    __shared__ __align__(16) __nv_bfloat16 sBh[2][BK][B_STR];
    __shared__ __align__(16) __nv_bfloat16 sBl[2][BK][B_STR];
    __shared__ float sBias[BN];
    __shared__ float sSc[HID];
    __shared__ float sSh[HID];

    const int K = layer ? 256 : 128;
    const int KCH = K / BK;            // 4 or 8
    const int NCH = 3 * KCH;           // 12 or 24
    int tid = threadIdx.x;
    int wid = tid >> 5, lane = tid & 31;
    int m0 = blockIdx.x * BM;
    int n0b = blockIdx.y * BN;
    int wm = wid >> 2;
    int wn = wid & 3;

    if (tid < BN) sBias[tid] = ba[n0b + tid] + bb[n0b + tid];
    if (layer) { sSc[tid] = g_sc[tid]; sSh[tid] = g_sh[tid]; }

    const __nv_bfloat16* Wh = layer ? g_Wh2 : g_Wh1;
    const __nv_bfloat16* Wl = layer ? g_Wl2 : g_Wl1;
    const float* A0 = g_mean_f;
    const float* A1 = g_mean_b;
    const float* A2 = layer ? g_h1 : xin;

    uint32_t ahBase = smem_u32(&sAh[0][0]);
    uint32_t alBase = smem_u32(&sAl[0][0]);

    int aRow = tid >> 2, aCg = tid & 3;       // A fill: row 0..63, 8-col group
    int bK = tid >> 3, bN = (tid & 7) * 16;   // B fill: k-row 0..31, 16-col group
    int gr = m0 + aRow;
    bool rowOK = (gr < N_NODES);

    uint32_t bhS0 = smem_u32(&sBh[0][bK][bN]);
    uint32_t bhS1 = smem_u32(&sBh[1][bK][bN]);
    uint32_t blS0 = smem_u32(&sBl[0][bK][bN]);
    uint32_t blS1 = smem_u32(&sBl[1][bK][bN]);

    float acc[2][4][4];
#pragma unroll
    for (int i = 0; i < 2; i++)
#pragma unroll
        for (int j = 0; j < 4; j++)
#pragma unroll
            for (int q = 0; q < 4; q++) acc[i][j][q] = 0.f;

    // ---- prologue: B chunk 0 via cp.async, A chunk 0 to regs
    {
        size_t gidx = (size_t)bK * HID + n0b + bN;
        cp_async16(bhS0, Wh + gidx);
        cp_async16(bhS0 + 16, Wh + gidx + 8);
        cp_async16(blS0, Wl + gidx);
        cp_async16(blS0 + 16, Wl + gidx + 8);
        CP_COMMIT();
    }
    float4 v0 = make_float4(0.f, 0.f, 0.f, 0.f), v1 = v0;
    if (rowOK) {
        const float* src = A0 + (size_t)gr * K + aCg * 8;
        v0 = *reinterpret_cast<const float4*>(src);
        v1 = *reinterpret_cast<const float4*>(src + 4);
    }
    CP_WAIT0();
    __syncthreads();

    for (int c = 0; c < NCH; c++) {
        int p = c & 1;
        int seg = c / KCH, kc = c - seg * KCH;
        // ---- convert A chunk c (in regs) -> smem hi/lo
        {
            float4 w0 = v0, w1 = v1;
            if (layer && seg == 2) {
                int cb = kc * BK + aCg * 8;
                w0.x = fmaxf(w0.x * sSc[cb]     + sSh[cb],     0.f);
                w0.y = fmaxf(w0.y * sSc[cb + 1] + sSh[cb + 1], 0.f);
                w0.z = fmaxf(w0.z * sSc[cb + 2] + sSh[cb + 2], 0.f);
                w0.w = fmaxf(w0.w * sSc[cb + 3] + sSh[cb + 3], 0.f);
                w1.x = fmaxf(w1.x * sSc[cb + 4] + sSh[cb + 4], 0.f);
                w1.y = fmaxf(w1.y * sSc[cb + 5] + sSh[cb + 5], 0.f);
                w1.z = fmaxf(w1.z * sSc[cb + 6] + sSh[cb + 6], 0.f);
                w1.w = fmaxf(w1.w * sSc[cb + 7] + sSh[cb + 7], 0.f);
            }
            uint4 uh, ul;
            split2(w0.x, w0.y, uh.x, ul.x);
            split2(w0.z, w0.w, uh.y, ul.y);
            split2(w1.x, w1.y, uh.z, ul.z);
            split2(w1.z, w1.w, uh.w, ul.w);
            *reinterpret_cast<uint4*>(&sAh[aRow][aCg * 8]) = uh;
            *reinterpret_cast<uint4*>(&sAl[aRow][aCg * 8]) = ul;
        }
        // ---- prefetch chunk c+1: B via cp.async (stage p^1), A to regs
        if (c + 1 < NCH) {
            size_t gidx = (size_t)((c + 1) * BK + bK) * HID + n0b + bN;
            uint32_t bh = p ? bhS0 : bhS1;
            uint32_t bl = p ? blS0 : blS1;
            cp_async16(bh, Wh + gidx);
            cp_async16(bh + 16, Wh + gidx + 8);
            cp_async16(bl, Wl + gidx);
            cp_async16(bl + 16, Wl + gidx + 8);
            CP_COMMIT();
            int seg2 = (c + 1) / KCH, kc2 = (c + 1) - seg2 * KCH;
            const float* A = (seg2 == 0) ? A0 : (seg2 == 1) ? A1 : A2;
            if (rowOK) {
                const float* src = A + (size_t)gr * K + kc2 * BK + aCg * 8;
                v0 = *reinterpret_cast<const float4*>(src);
                v1 = *reinterpret_cast<const float4*>(src + 4);
            }
        }
        __syncthreads();   // sA ready; sB stage p ready (waited previous iter)
        // ---- MMA over 2 k-steps of 16
        uint32_t bhBase = smem_u32(&sBh[p][0][0]);
        uint32_t blBase = smem_u32(&sBl[p][0][0]);
#pragma unroll
        for (int ks = 0; ks < 2; ks++) {
            uint32_t ah[2][4], al[2][4], bh[4][2], bl[4][2];
#pragma unroll
            for (int mf = 0; mf < 2; mf++) {
                uint32_t off = ((wm * 32 + mf * 16 + (lane & 15)) * A_STR
                                + ks * 16 + (lane >> 4) * 8) * 2;
                ldsm4(ahBase + off, ah[mf][0], ah[mf][1], ah[mf][2], ah[mf][3]);
                ldsm4(alBase + off, al[mf][0], al[mf][1], al[mf][2], al[mf][3]);
            }
#pragma unroll
            for (int np = 0; np < 2; np++) {
                uint32_t off = ((ks * 16 + (lane & 15)) * B_STR
                                + wn * 32 + np * 16 + (lane >> 4) * 8) * 2;
                ldsm4t(bhBase + off, bh[np * 2][0], bh[np * 2][1],
                       bh[np * 2 + 1][0], bh[np * 2 + 1][1]);
                ldsm4t(blBase + off, bl[np * 2][0], bl[np * 2][1],
                       bl[np * 2 + 1][0], bl[np * 2 + 1][1]);
            }
#pragma unroll
            for (int mf = 0; mf < 2; mf++)
#pragma unroll
                for (int nf = 0; nf < 4; nf++) {
                    mma_bf16(acc[mf][nf], ah[mf], bh[nf]);
                    mma_bf16(acc[mf][nf], ah[mf], bl[nf]);
                    mma_bf16(acc[mf][nf], al[mf], bh[nf]);
                }
        }
        CP_WAIT0();        // next B stage landed
        __syncthreads();   // safe to overwrite sA next iteration
    }

    // ---- epilogue -------------------------------------------------------------
    // layer 0: bias + store fp32 h1 + fused BN stats.
    // layer 1: bias + fused BN stats + per-column max/min (NO store of h2).
    float* C = g_h1;
#pragma unroll
    for (int nf = 0; nf < 4; nf++) {
        int cl = wn * 32 + nf * 8 + (lane & 3) * 2;
        float b0 = sBias[cl], b1 = sBias[cl + 1];
        float s0 = 0.f, s1 = 0.f, q0 = 0.f, q1 = 0.f;
        float mx0 = -3.4e38f, mx1 = -3.4e38f, mn0 = 3.4e38f, mn1 = 3.4e38f;
#pragma unroll
        for (int mf = 0; mf < 2; mf++) {
            int row0 = m0 + wm * 32 + mf * 16 + (lane >> 2);
            int row1 = row0 + 8;
            float v00 = acc[mf][nf][0] + b0, v01 = acc[mf][nf][1] + b1;
            float v10 = acc[mf][nf][2] + b0, v11 = acc[mf][nf][3] + b1;
            if (row0 < N_NODES) {
                if (!layer)
                    *reinterpret_cast<float2*>(C + (size_t)row0 * HID + n0b + cl) = make_float2(v00, v01);
                s0 += v00; q0 += v00 * v00; s1 += v01; q1 += v01 * v01;
                mx0 = fmaxf(mx0, v00); mn0 = fminf(mn0, v00);
                mx1 = fmaxf(mx1, v01); mn1 = fminf(mn1, v01);
            }
            if (row1 < N_NODES) {
                if (!layer)
                    *reinterpret_cast<float2*>(C + (size_t)row1 * HID + n0b + cl) = make_float2(v10, v11);
                s0 += v10; q0 += v10 * v10; s1 += v11; q1 += v11 * v11;
                mx0 = fmaxf(mx0, v10); mn0 = fminf(mn0, v10);
                mx1 = fmaxf(mx1, v11); mn1 = fminf(mn1, v11);
            }
        }
#pragma unroll
        for (int o = 4; o < 32; o <<= 1) {
            s0 += __shfl_xor_sync(0xFFFFFFFFu, s0, o);
            s1 += __shfl_xor_sync(0xFFFFFFFFu, s1, o);
            q0 += __shfl_xor_sync(0xFFFFFFFFu, q0, o);
            q1 += __shfl_xor_sync(0xFFFFFFFFu, q1, o);
            if (layer) {
                mx0 = fmaxf(mx0, __shfl_xor_sync(0xFFFFFFFFu, mx0, o));
                mx1 = fmaxf(mx1, __shfl_xor_sync(0xFFFFFFFFu, mx1, o));
                mn0 = fminf(mn0, __shfl_xor_sync(0xFFFFFFFFu, mn0, o));
                mn1 = fminf(mn1, __shfl_xor_sync(0xFFFFFFFFu, mn1, o));
            }
        }
        if (lane < 4) {
            atomicAdd(&g_stats[n0b + cl], s0);
            atomicAdd(&g_stats[n0b + cl + 1], s1);
            atomicAdd(&g_stats[HID + n0b + cl], q0);
            atomicAdd(&g_stats[HID + n0b + cl + 1], q1);
            if (layer) {
                atomicMax(&g_cmax[n0b + cl], fenc(mx0));
                atomicMax(&g_cmax[n0b + cl + 1], fenc(mx1));
                atomicMin(&g_cmin[n0b + cl], fenc(mn0));
                atomicMin(&g_cmin[n0b + cl + 1], fenc(mn1));
            }
        }
    }
}

// ---------------- batchnorm finalize ----------------------------------------------
// layer 0: compute sc/sh, re-zero stats for layer 2, init column max/min.
// layer 1: compute sc/sh, write final out[c] from column max/min (monotone affine).
__global__ void k_bnfinal(const float* __restrict__ g, const float* __restrict__ beta,
                          int layer, float* __restrict__ out) {
    int c = threadIdx.x;
    float mu = g_stats[c] * (1.0f / N_NODES);
    float var = g_stats[HID + c] * (1.0f / N_NODES) - mu * mu;
    float sc = g[c] * rsqrtf(var + BN_EPS);
    float sh = beta[c] - mu * sc;
    g_sc[c] = sc;
    g_sh[c] = sh;
    if (layer == 0) {
        g_stats[c] = 0.f;
        g_stats[HID + c] = 0.f;
        g_cmax[c] = 0u;               // < encoding of any float
        g_cmin[c] = 0xFFFFFFFFu;      // > encoding of any float
    } else {
        float vmax = fdec(g_cmax[c]);
        float vmin = fdec(g_cmin[c]);
        float vext = (sc >= 0.f) ? vmax : vmin;
        out[c] = fmaxf(vext * sc + sh, 0.f);
    }
}

// ---------------- launch ----------------------------------------------------------
extern "C" void kernel_launch(void* const* d_in, const int* in_sizes, int n_in,
                              void* d_out, int out_size) {
    const float* x     = (const float*)d_in[0];
    const int*   ei32  = (const int*)d_in[1];
    const float* Wl_f1 = (const float*)d_in[2];
    const float* bl_f1 = (const float*)d_in[3];
    const float* Wr_f1 = (const float*)d_in[4];
    const float* Wl_b1 = (const float*)d_in[5];
    const float* bl_b1 = (const float*)d_in[6];
    const float* Wr_b1 = (const float*)d_in[7];
    const float* Wl_f2 = (const float*)d_in[8];
    const float* bl_f2 = (const float*)d_in[9];
    const float* Wr_f2 = (const float*)d_in[10];
    const float* Wl_b2 = (const float*)d_in[11];
    const float* bl_b2 = (const float*)d_in[12];
    const float* Wr_b2 = (const float*)d_in[13];
    const float* g1    = (const float*)d_in[14];
    const float* beta1 = (const float*)d_in[15];
    const float* g2    = (const float*)d_in[16];
    const float* beta2 = (const float*)d_in[17];
    float* out = (float*)d_out;

    // ---- CSR build (scan_mid also zeroes layer-1 BN stats) ----
    k_detect<<<1, 256>>>(ei32);
    k_zero_deg<<<(N_NODES + 1023) / 1024, 1024>>>();
    k_count<<<(N_EDGES + 255) / 256, 256>>>(ei32);
    k_scan_partial<<<SCAN_B, SCAN_T>>>();
    k_scan_mid<<<1, 256>>>();
    k_scan_final<<<SCAN_B, SCAN_T>>>();
    k_scatter<<<(N_EDGES + 255) / 256, 256>>>(ei32);

    // ---- weight prep ----
    k_prepW<<<3 * 128, 256>>>(Wl_f1, Wl_b1, Wr_f1, Wr_b1, 0);
    k_prepW<<<3 * 256, 256>>>(Wl_f2, Wl_b2, Wr_f2, Wr_b2, 1);

    const int aggBlocks = (2 * N_NODES + 7) / 8;        // both dirs in one launch
    dim3 gemmGrid((N_NODES + BM - 1) / BM, HID / BN);   // (782, 2)

    // ---- layer 1 ----
    k_agg<D_IN><<<aggBlocks, 256>>>(x, 0);
    k_gemm_mma<<<gemmGrid, 256>>>(x, bl_f1, bl_b1, 0);
    k_bnfinal<<<1, HID>>>(g1, beta1, 0, out);   // sc/sh; re-zero stats; init max/min

    // ---- layer 2 (affine+relu on the fly; h2 never materialized) ----
    k_agg<HID><<<aggBlocks, 256>>>(x, 1);
    k_gemm_mma<<<gemmGrid, 256>>>(x, bl_f2, bl_b2, 1);
    k_bnfinal<<<1, HID>>>(g2, beta2, 1, out);   // out[] written directly

    (void)in_sizes; (void)n_in; (void)out_size;
}